// round 1
// baseline (speedup 1.0000x reference)
#include <cuda_runtime.h>
#include <math.h>

// Problem constants
#define BB   2
#define NN   2048
#define EE   1024
#define HH   16
#define DD   64
#define MLPD 4096
#define MR   (BB * NN)   // 4096 token rows

// ---------------- scratch (static device globals; no allocation) ----------------
__device__ float g_h[MR * EE];          // LN output (reused for both LNs)
__device__ float g_qkv[MR * 3 * EE];    // QKV projection output
__device__ float g_attn[MR * EE];       // attention output [B,N,E]
__device__ float g_x1[MR * EE];         // x + attn proj (residual 1)
__device__ float g_mlp[MR * MLPD];      // GELU(fc1) output

// ---------------- LayerNorm: one block per row of 1024 -------------------------
__global__ void ln_kernel(const float* __restrict__ x, const float* __restrict__ g,
                          const float* __restrict__ beta, float* __restrict__ out) {
    __shared__ float sh[8];
    const int row = blockIdx.x;
    const int tid = threadIdx.x;
    const float4 v = ((const float4*)(x + (size_t)row * EE))[tid];

    // --- sum reduce ---
    float s = v.x + v.y + v.z + v.w;
    #pragma unroll
    for (int o = 16; o; o >>= 1) s += __shfl_down_sync(0xffffffffu, s, o);
    if ((tid & 31) == 0) sh[tid >> 5] = s;
    __syncthreads();
    if (tid < 32) {
        float t = (tid < 8) ? sh[tid] : 0.f;
        #pragma unroll
        for (int o = 4; o; o >>= 1) t += __shfl_down_sync(0xffffffffu, t, o);
        if (tid == 0) sh[0] = t;
    }
    __syncthreads();
    const float mu = sh[0] * (1.0f / EE);
    __syncthreads();

    // --- sumsq reduce ---
    float dx = v.x - mu, dy = v.y - mu, dz = v.z - mu, dw = v.w - mu;
    float q = dx * dx + dy * dy + dz * dz + dw * dw;
    #pragma unroll
    for (int o = 16; o; o >>= 1) q += __shfl_down_sync(0xffffffffu, q, o);
    if ((tid & 31) == 0) sh[tid >> 5] = q;
    __syncthreads();
    if (tid < 32) {
        float t = (tid < 8) ? sh[tid] : 0.f;
        #pragma unroll
        for (int o = 4; o; o >>= 1) t += __shfl_down_sync(0xffffffffu, t, o);
        if (tid == 0) sh[0] = t;
    }
    __syncthreads();
    const float rstd = rsqrtf(sh[0] * (1.0f / EE) + 1e-5f);

    const float4 gv = ((const float4*)g)[tid];
    const float4 bv = ((const float4*)beta)[tid];
    float4 o;
    o.x = dx * rstd * gv.x + bv.x;
    o.y = dy * rstd * gv.y + bv.y;
    o.z = dz * rstd * gv.z + bv.z;
    o.w = dw * rstd * gv.w + bv.w;
    ((float4*)(out + (size_t)row * EE))[tid] = o;
}

// ---------------- SGEMM 128x128x8, 256 threads, 8x8 per-thread -----------------
// C[M,N] = A[M,K] @ B[K,N] + bias[N], epilogue:
//   EPI=0: none extra, EPI=1: exact GELU, EPI=2: + res[M,N]
template <int EPI>
__global__ __launch_bounds__(256, 2)
void sgemm_kernel(const float* __restrict__ A, const float* __restrict__ Bm,
                  const float* __restrict__ bias, const float* __restrict__ res,
                  float* __restrict__ C, int M, int N, int K) {
    __shared__ float As[8][128];
    __shared__ float Bs[8][128];
    const int tid = threadIdx.x;
    const int bm = blockIdx.y << 7;
    const int bn = blockIdx.x << 7;

    const int arow = tid >> 1, acol = (tid & 1) << 2;   // A tile: 128 rows x 8 cols
    const int brow = tid >> 5, bcol = (tid & 31) << 2;  // B tile: 8 rows x 128 cols

    const float* Ap = A + (size_t)(bm + arow) * K + acol;
    const float* Bp = Bm + (size_t)brow * N + bn + bcol;

    const int tx = tid & 15, ty = tid >> 4;  // 16x16 thread grid, 8x8 micro-tile

    float acc[8][8];
    #pragma unroll
    for (int i = 0; i < 8; i++)
        #pragma unroll
        for (int j = 0; j < 8; j++) acc[i][j] = 0.f;

    for (int k0 = 0; k0 < K; k0 += 8) {
        const float4 a4 = *(const float4*)Ap; Ap += 8;
        const float4 b4 = *(const float4*)Bp; Bp += (size_t)8 * N;
        As[acol + 0][arow] = a4.x;
        As[acol + 1][arow] = a4.y;
        As[acol + 2][arow] = a4.z;
        As[acol + 3][arow] = a4.w;
        *(float4*)&Bs[brow][bcol] = b4;
        __syncthreads();

        #pragma unroll
        for (int kk = 0; kk < 8; kk++) {
            const float4 a0 = *(const float4*)&As[kk][ty * 8];
            const float4 a1 = *(const float4*)&As[kk][ty * 8 + 4];
            const float4 b0 = *(const float4*)&Bs[kk][tx * 8];
            const float4 b1 = *(const float4*)&Bs[kk][tx * 8 + 4];
            const float av[8] = {a0.x, a0.y, a0.z, a0.w, a1.x, a1.y, a1.z, a1.w};
            const float bv[8] = {b0.x, b0.y, b0.z, b0.w, b1.x, b1.y, b1.z, b1.w};
            #pragma unroll
            for (int i = 0; i < 8; i++)
                #pragma unroll
                for (int j = 0; j < 8; j++) acc[i][j] += av[i] * bv[j];
        }
        __syncthreads();
    }

    // epilogue
    float bi[8];
    #pragma unroll
    for (int j = 0; j < 8; j++) bi[j] = bias[bn + tx * 8 + j];

    #pragma unroll
    for (int i = 0; i < 8; i++) {
        const int row = bm + ty * 8 + i;
        float* cp = C + (size_t)row * N + bn + tx * 8;
        const float* rp = (EPI == 2) ? (res + (size_t)row * N + bn + tx * 8) : nullptr;
        #pragma unroll
        for (int j = 0; j < 8; j++) {
            float c = acc[i][j] + bi[j];
            if (EPI == 1) c = 0.5f * c * (1.0f + erff(c * 0.70710678118654752f));
            if (EPI == 2) c += rp[j];
            cp[j] = c;
        }
    }
}

// ---------------- Flash attention (fp32), 1 query per thread -------------------
// qkv layout per row: [3, H, D] -> Q at +0, K at +1024, V at +2048
__global__ __launch_bounds__(128, 2)
void attn_kernel(const float* __restrict__ qkv, float* __restrict__ out) {
    __shared__ float Ks[64 * 64];
    __shared__ float Vs[64 * 64];
    const int bh = blockIdx.y;
    const int b = bh >> 4;
    const int h = bh & 15;
    const int qi = blockIdx.x * 128 + threadIdx.x;

    const float4* qp = (const float4*)(qkv + ((size_t)(b * NN + qi)) * 3072 + h * 64);
    float4 q[16];
    #pragma unroll
    for (int i = 0; i < 16; i++) q[i] = qp[i];

    float4 acc[16];
    #pragma unroll
    for (int i = 0; i < 16; i++) acc[i] = make_float4(0.f, 0.f, 0.f, 0.f);
    float m = -1e30f, l = 0.f;
    const float scale = 0.125f;  // D^-0.5, D=64

    for (int kt = 0; kt < NN; kt += 64) {
        __syncthreads();
        // cooperative coalesced load of K/V tiles: 64 rows x 16 float4
        #pragma unroll
        for (int it = 0; it < 8; it++) {
            const int e = it * 128 + threadIdx.x;
            const int r = e >> 4, c = e & 15;
            const size_t base = ((size_t)(b * NN + kt + r)) * 3072 + h * 64;
            ((float4*)Ks)[e] = *((const float4*)(qkv + base + 1024) + c);
            ((float4*)Vs)[e] = *((const float4*)(qkv + base + 2048) + c);
        }
        __syncthreads();

        #pragma unroll 1
        for (int j = 0; j < 64; j++) {
            const float4* kr = (const float4*)(Ks + j * 64);
            float s = 0.f;
            #pragma unroll
            for (int i = 0; i < 16; i++) {
                const float4 kk = kr[i];
                s += q[i].x * kk.x + q[i].y * kk.y + q[i].z * kk.z + q[i].w * kk.w;
            }
            s *= scale;
            float p;
            if (s > m) {  // lazy rescale: amortized O(log N) per row
                const float f = __expf(m - s);
                l *= f;
                #pragma unroll
                for (int i = 0; i < 16; i++) {
                    acc[i].x *= f; acc[i].y *= f; acc[i].z *= f; acc[i].w *= f;
                }
                m = s;
                p = 1.f;
            } else {
                p = __expf(s - m);
            }
            l += p;
            const float4* vr = (const float4*)(Vs + j * 64);
            #pragma unroll
            for (int i = 0; i < 16; i++) {
                const float4 vv = vr[i];
                acc[i].x += p * vv.x; acc[i].y += p * vv.y;
                acc[i].z += p * vv.z; acc[i].w += p * vv.w;
            }
        }
    }

    const float inv = 1.f / l;
    float4* op = (float4*)(out + ((size_t)(b * NN + qi)) * EE + h * 64);
    #pragma unroll
    for (int i = 0; i < 16; i++) {
        float4 o;
        o.x = acc[i].x * inv; o.y = acc[i].y * inv;
        o.z = acc[i].z * inv; o.w = acc[i].w * inv;
        op[i] = o;
    }
}

// ---------------- host launch ---------------------------------------------------
extern "C" void kernel_launch(void* const* d_in, const int* in_sizes, int n_in,
                              void* d_out, int out_size) {
    const float* x      = (const float*)d_in[0];
    const float* w_qkv  = (const float*)d_in[1];
    const float* b_qkv  = (const float*)d_in[2];
    const float* w_proj = (const float*)d_in[3];
    const float* b_proj = (const float*)d_in[4];
    const float* g1     = (const float*)d_in[5];
    const float* beta1  = (const float*)d_in[6];
    const float* g2     = (const float*)d_in[7];
    const float* beta2  = (const float*)d_in[8];
    const float* w_fc1  = (const float*)d_in[9];
    const float* b_fc1  = (const float*)d_in[10];
    const float* w_fc2  = (const float*)d_in[11];
    const float* b_fc2  = (const float*)d_in[12];
    float* out = (float*)d_out;

    float *h, *qkv, *attn, *x1, *mlp;
    cudaGetSymbolAddress((void**)&h,    g_h);
    cudaGetSymbolAddress((void**)&qkv,  g_qkv);
    cudaGetSymbolAddress((void**)&attn, g_attn);
    cudaGetSymbolAddress((void**)&x1,   g_x1);
    cudaGetSymbolAddress((void**)&mlp,  g_mlp);

    // 1. h = LN(x; g1, beta1)
    ln_kernel<<<MR, 256>>>(x, g1, beta1, h);
    // 2. qkv = h @ w_qkv + b_qkv                      [4096 x 3072], K=1024
    sgemm_kernel<0><<<dim3(3 * EE / 128, MR / 128), 256>>>(
        h, w_qkv, b_qkv, nullptr, qkv, MR, 3 * EE, EE);
    // 3. attention -> attn [B,N,E]
    attn_kernel<<<dim3(NN / 128, BB * HH), 128>>>(qkv, attn);
    // 4. x1 = attn @ w_proj + b_proj + x              [4096 x 1024], K=1024
    sgemm_kernel<2><<<dim3(EE / 128, MR / 128), 256>>>(
        attn, w_proj, b_proj, x, x1, MR, EE, EE);
    // 5. h = LN(x1; g2, beta2)
    ln_kernel<<<MR, 256>>>(x1, g2, beta2, h);
    // 6. mlp = gelu(h @ w_fc1 + b_fc1)                [4096 x 4096], K=1024
    sgemm_kernel<1><<<dim3(MLPD / 128, MR / 128), 256>>>(
        h, w_fc1, b_fc1, nullptr, mlp, MR, MLPD, EE);
    // 7. out = mlp @ w_fc2 + b_fc2 + x1               [4096 x 1024], K=4096
    sgemm_kernel<2><<<dim3(EE / 128, MR / 128), 256>>>(
        mlp, w_fc2, b_fc2, x1, out, MR, EE, MLPD);
}

// round 3
// speedup vs baseline: 1.6031x; 1.6031x over previous
#include <cuda_runtime.h>
#include <math.h>
#include <stdint.h>

// Problem constants
#define BB   2
#define NN   2048
#define EE   1024
#define HH   16
#define MLPD 4096
#define MR   (BB * NN)   // 4096 token rows

// ---------------- scratch (static device globals; no allocation) ----------------
__device__ float g_h[MR * EE];
__device__ float g_qkv[MR * 3 * EE];
__device__ float g_attn[MR * EE];
__device__ float g_x1[MR * EE];
__device__ float g_mlp[(size_t)MR * MLPD];
// transposed weights, [N,K] K-major
__device__ float g_wqkvT[3 * EE * EE];
__device__ float g_wprojT[EE * EE];
__device__ float g_wfc1T[(size_t)MLPD * EE];
__device__ float g_wfc2T[(size_t)EE * MLPD];

// ======================= helpers =================================
__device__ __forceinline__ uint32_t smem_u32(const void* p) {
    uint32_t a;
    asm("{ .reg .u64 t; cvta.to.shared.u64 t, %1; cvt.u32.u64 %0, t; }" : "=r"(a) : "l"(p));
    return a;
}
__device__ __forceinline__ float to_tf32(float x) {
    float r;
    asm("cvt.rna.tf32.f32 %0, %1;" : "=f"(r) : "f"(x));
    return r;
}
__device__ __forceinline__ void cp16(uint32_t dst, const void* src) {
    asm volatile("cp.async.cg.shared.global [%0], [%1], 16;" :: "r"(dst), "l"(src));
}
#define CP_COMMIT() asm volatile("cp.async.commit_group;" ::: "memory")
#define CP_WAIT1()  asm volatile("cp.async.wait_group 1;" ::: "memory")

__device__ __forceinline__ void mma_tf32(float* c, const uint32_t* a, const uint32_t* b) {
    asm volatile(
        "mma.sync.aligned.m16n8k8.row.col.f32.tf32.tf32.f32 "
        "{%0,%1,%2,%3}, {%4,%5,%6,%7}, {%8,%9}, {%0,%1,%2,%3};"
        : "+f"(c[0]), "+f"(c[1]), "+f"(c[2]), "+f"(c[3])
        : "r"(a[0]), "r"(a[1]), "r"(a[2]), "r"(a[3]), "r"(b[0]), "r"(b[1]));
}

// ---------------- transpose: [R,C] -> [C,R], output rounded to tf32 -------------
__global__ void transpose_kernel(const float* __restrict__ in, float* __restrict__ out,
                                 int R, int C) {
    __shared__ float t[32][33];
    const int c = blockIdx.x * 32 + threadIdx.x;
    const int r0 = blockIdx.y * 32;
    #pragma unroll
    for (int i = threadIdx.y; i < 32; i += 8)
        t[i][threadIdx.x] = in[(size_t)(r0 + i) * C + c];
    __syncthreads();
    const int rc = blockIdx.y * 32 + threadIdx.x;
    const int c0 = blockIdx.x * 32;
    #pragma unroll
    for (int i = threadIdx.y; i < 32; i += 8)
        out[(size_t)(c0 + i) * R + rc] = to_tf32(t[threadIdx.x][i]);
}

// ---------------- LayerNorm, output rounded to tf32 -----------------------------
__global__ void ln_kernel(const float* __restrict__ x, const float* __restrict__ g,
                          const float* __restrict__ beta, float* __restrict__ out) {
    __shared__ float sh[8];
    const int row = blockIdx.x;
    const int tid = threadIdx.x;
    const float4 v = ((const float4*)(x + (size_t)row * EE))[tid];

    float s = v.x + v.y + v.z + v.w;
    #pragma unroll
    for (int o = 16; o; o >>= 1) s += __shfl_down_sync(0xffffffffu, s, o);
    if ((tid & 31) == 0) sh[tid >> 5] = s;
    __syncthreads();
    if (tid < 32) {
        float t = (tid < 8) ? sh[tid] : 0.f;
        #pragma unroll
        for (int o = 4; o; o >>= 1) t += __shfl_down_sync(0xffffffffu, t, o);
        if (tid == 0) sh[0] = t;
    }
    __syncthreads();
    const float mu = sh[0] * (1.0f / EE);
    __syncthreads();

    float dx = v.x - mu, dy = v.y - mu, dz = v.z - mu, dw = v.w - mu;
    float q = dx * dx + dy * dy + dz * dz + dw * dw;
    #pragma unroll
    for (int o = 16; o; o >>= 1) q += __shfl_down_sync(0xffffffffu, q, o);
    if ((tid & 31) == 0) sh[tid >> 5] = q;
    __syncthreads();
    if (tid < 32) {
        float t = (tid < 8) ? sh[tid] : 0.f;
        #pragma unroll
        for (int o = 4; o; o >>= 1) t += __shfl_down_sync(0xffffffffu, t, o);
        if (tid == 0) sh[0] = t;
    }
    __syncthreads();
    const float rstd = rsqrtf(sh[0] * (1.0f / EE) + 1e-5f);

    const float4 gv = ((const float4*)g)[tid];
    const float4 bv = ((const float4*)beta)[tid];
    float4 o;
    o.x = to_tf32(dx * rstd * gv.x + bv.x);
    o.y = to_tf32(dy * rstd * gv.y + bv.y);
    o.z = to_tf32(dz * rstd * gv.z + bv.z);
    o.w = to_tf32(dw * rstd * gv.w + bv.w);
    ((float4*)(out + (size_t)row * EE))[tid] = o;
}

// ---------------- tf32 mma.sync GEMM --------------------------------------------
// C[M,N] = A[M,K] @ BT[N,K]^T + bias; EPI: 0=none, 1=GELU(+tf32 round), 2=+res
// CTA 128x128, 8 warps (2m x 4n), warp tile 64x32, K-chunk 32, double-buffered.
#define ASTRIDE 36                       // padded row stride (floats), conflict-free
#define STAGEF  (2 * 128 * ASTRIDE)      // floats per stage (A+B)
#define GEMM_SMEM_BYTES (2 * STAGEF * 4) // 73728 bytes

__device__ __forceinline__ void issue_tile(const float* __restrict__ A,
                                           const float* __restrict__ BT,
                                           float* sA, float* sB,
                                           int bm, int bn, int kc, int K, int tid) {
    #pragma unroll
    for (int p = 0; p < 4; p++) {
        const int e = p * 256 + tid;
        const int row = e >> 3, ch = e & 7;
        cp16(smem_u32(sA + row * ASTRIDE + ch * 4),
             A + (size_t)(bm + row) * K + kc * 32 + ch * 4);
        cp16(smem_u32(sB + row * ASTRIDE + ch * 4),
             BT + (size_t)(bn + row) * K + kc * 32 + ch * 4);
    }
}

template <int EPI>
__global__ __launch_bounds__(256, 1)
void gemm_mma(const float* __restrict__ A, const float* __restrict__ BT,
              const float* __restrict__ bias, const float* __restrict__ res,
              float* __restrict__ C, int M, int N, int K) {
    extern __shared__ __align__(16) float smem[];
    const int tid  = threadIdx.x;
    const int lane = tid & 31, warp = tid >> 5;
    const int wm = warp >> 2, wn = warp & 3;     // 2 x 4 warp grid
    const int gq = lane >> 2, tq = lane & 3;     // quad row / quad lane
    const int bm = blockIdx.y << 7;
    const int bn = blockIdx.x << 7;
    const int NC = K >> 5;

    float* As[2] = { smem,          smem + STAGEF };
    float* Bs[2] = { smem + 128 * ASTRIDE, smem + STAGEF + 128 * ASTRIDE };

    float c[4][4][4];
    #pragma unroll
    for (int i = 0; i < 4; i++)
        #pragma unroll
        for (int j = 0; j < 4; j++)
            #pragma unroll
            for (int k = 0; k < 4; k++) c[i][j][k] = 0.f;

    issue_tile(A, BT, As[0], Bs[0], bm, bn, 0, K, tid); CP_COMMIT();
    issue_tile(A, BT, As[1], Bs[1], bm, bn, 1, K, tid); CP_COMMIT();

    for (int kc = 0; kc < NC; kc++) {
        const int b = kc & 1;
        CP_WAIT1();
        __syncthreads();
        const float* sa = As[b] + (wm * 64 + gq) * ASTRIDE;
        const float* sb = Bs[b] + (wn * 32 + gq) * ASTRIDE;
        #pragma unroll
        for (int ks = 0; ks < 4; ks++) {
            uint32_t af[4][4], bf[4][2];
            #pragma unroll
            for (int mt = 0; mt < 4; mt++) {
                const float* ap = sa + mt * 16 * ASTRIDE + ks * 8 + tq;
                af[mt][0] = __float_as_uint(ap[0]);
                af[mt][1] = __float_as_uint(ap[8 * ASTRIDE]);
                af[mt][2] = __float_as_uint(ap[4]);
                af[mt][3] = __float_as_uint(ap[8 * ASTRIDE + 4]);
            }
            #pragma unroll
            for (int nt = 0; nt < 4; nt++) {
                const float* bp = sb + nt * 8 * ASTRIDE + ks * 8 + tq;
                bf[nt][0] = __float_as_uint(bp[0]);
                bf[nt][1] = __float_as_uint(bp[4]);
            }
            #pragma unroll
            for (int mt = 0; mt < 4; mt++)
                #pragma unroll
                for (int nt = 0; nt < 4; nt++)
                    mma_tf32(c[mt][nt], af[mt], bf[nt]);
        }
        __syncthreads();
        if (kc + 2 < NC) issue_tile(A, BT, As[b], Bs[b], bm, bn, kc + 2, K, tid);
        CP_COMMIT();
    }

    // ---- epilogue ----
    #pragma unroll
    for (int mt = 0; mt < 4; mt++) {
        const int row0 = bm + wm * 64 + mt * 16 + gq;
        #pragma unroll
        for (int nt = 0; nt < 4; nt++) {
            const int col = bn + wn * 32 + nt * 8 + 2 * tq;
            const float bx = bias[col], by = bias[col + 1];
            #pragma unroll
            for (int half = 0; half < 2; half++) {
                const int row = row0 + half * 8;
                float vx = c[mt][nt][half * 2 + 0] + bx;
                float vy = c[mt][nt][half * 2 + 1] + by;
                if (EPI == 1) {
                    vx = 0.5f * vx * (1.0f + erff(vx * 0.70710678118654752f));
                    vy = 0.5f * vy * (1.0f + erff(vy * 0.70710678118654752f));
                    vx = to_tf32(vx); vy = to_tf32(vy);
                }
                if (EPI == 2) {
                    const float2 rv = *(const float2*)(res + (size_t)row * N + col);
                    vx += rv.x; vy += rv.y;
                }
                float2 o; o.x = vx; o.y = vy;
                *(float2*)(C + (size_t)row * N + col) = o;
            }
        }
    }
}

// ---------------- Flash attention (fp32), output rounded to tf32 ---------------
__global__ __launch_bounds__(128, 2)
void attn_kernel(const float* __restrict__ qkv, float* __restrict__ out) {
    __shared__ float Ks[64 * 64];
    __shared__ float Vs[64 * 64];
    const int bh = blockIdx.y;
    const int b = bh >> 4;
    const int h = bh & 15;
    const int qi = blockIdx.x * 128 + threadIdx.x;

    const float4* qp = (const float4*)(qkv + ((size_t)(b * NN + qi)) * 3072 + h * 64);
    float4 q[16];
    #pragma unroll
    for (int i = 0; i < 16; i++) q[i] = qp[i];

    float4 acc[16];
    #pragma unroll
    for (int i = 0; i < 16; i++) acc[i] = make_float4(0.f, 0.f, 0.f, 0.f);
    float m = -1e30f, l = 0.f;
    const float scale = 0.125f;

    for (int kt = 0; kt < NN; kt += 64) {
        __syncthreads();
        #pragma unroll
        for (int it = 0; it < 8; it++) {
            const int e = it * 128 + threadIdx.x;
            const int r = e >> 4, ccol = e & 15;
            const size_t base = ((size_t)(b * NN + kt + r)) * 3072 + h * 64;
            ((float4*)Ks)[e] = *((const float4*)(qkv + base + 1024) + ccol);
            ((float4*)Vs)[e] = *((const float4*)(qkv + base + 2048) + ccol);
        }
        __syncthreads();

        #pragma unroll 1
        for (int j = 0; j < 64; j++) {
            const float4* kr = (const float4*)(Ks + j * 64);
            float s = 0.f;
            #pragma unroll
            for (int i = 0; i < 16; i++) {
                const float4 kk = kr[i];
                s += q[i].x * kk.x + q[i].y * kk.y + q[i].z * kk.z + q[i].w * kk.w;
            }
            s *= scale;
            float p;
            if (s > m) {
                const float f = __expf(m - s);
                l *= f;
                #pragma unroll
                for (int i = 0; i < 16; i++) {
                    acc[i].x *= f; acc[i].y *= f; acc[i].z *= f; acc[i].w *= f;
                }
                m = s;
                p = 1.f;
            } else {
                p = __expf(s - m);
            }
            l += p;
            const float4* vr = (const float4*)(Vs + j * 64);
            #pragma unroll
            for (int i = 0; i < 16; i++) {
                const float4 vv = vr[i];
                acc[i].x += p * vv.x; acc[i].y += p * vv.y;
                acc[i].z += p * vv.z; acc[i].w += p * vv.w;
            }
        }
    }

    const float inv = 1.f / l;
    float4* op = (float4*)(out + ((size_t)(b * NN + qi)) * EE + h * 64);
    #pragma unroll
    for (int i = 0; i < 16; i++) {
        float4 o;
        o.x = to_tf32(acc[i].x * inv); o.y = to_tf32(acc[i].y * inv);
        o.z = to_tf32(acc[i].z * inv); o.w = to_tf32(acc[i].w * inv);
        op[i] = o;
    }
}

// ---------------- host launch ---------------------------------------------------
extern "C" void kernel_launch(void* const* d_in, const int* in_sizes, int n_in,
                              void* d_out, int out_size) {
    const float* x      = (const float*)d_in[0];
    const float* w_qkv  = (const float*)d_in[1];
    const float* b_qkv  = (const float*)d_in[2];
    const float* w_proj = (const float*)d_in[3];
    const float* b_proj = (const float*)d_in[4];
    const float* g1     = (const float*)d_in[5];
    const float* beta1  = (const float*)d_in[6];
    const float* g2     = (const float*)d_in[7];
    const float* beta2  = (const float*)d_in[8];
    const float* w_fc1  = (const float*)d_in[9];
    const float* b_fc1  = (const float*)d_in[10];
    const float* w_fc2  = (const float*)d_in[11];
    const float* b_fc2  = (const float*)d_in[12];
    float* out = (float*)d_out;

    float *h, *qkv, *attn, *x1, *mlp, *wqkvT, *wprojT, *wfc1T, *wfc2T;
    cudaGetSymbolAddress((void**)&h,      g_h);
    cudaGetSymbolAddress((void**)&qkv,    g_qkv);
    cudaGetSymbolAddress((void**)&attn,   g_attn);
    cudaGetSymbolAddress((void**)&x1,     g_x1);
    cudaGetSymbolAddress((void**)&mlp,    g_mlp);
    cudaGetSymbolAddress((void**)&wqkvT,  g_wqkvT);
    cudaGetSymbolAddress((void**)&wprojT, g_wprojT);
    cudaGetSymbolAddress((void**)&wfc1T,  g_wfc1T);
    cudaGetSymbolAddress((void**)&wfc2T,  g_wfc2T);

    cudaFuncSetAttribute(gemm_mma<0>, cudaFuncAttributeMaxDynamicSharedMemorySize, GEMM_SMEM_BYTES);
    cudaFuncSetAttribute(gemm_mma<1>, cudaFuncAttributeMaxDynamicSharedMemorySize, GEMM_SMEM_BYTES);
    cudaFuncSetAttribute(gemm_mma<2>, cudaFuncAttributeMaxDynamicSharedMemorySize, GEMM_SMEM_BYTES);

    // weight transposes -> [N,K] (tf32-rounded)
    transpose_kernel<<<dim3(3 * EE / 32, EE / 32), dim3(32, 8)>>>(w_qkv, wqkvT, EE, 3 * EE);
    transpose_kernel<<<dim3(EE / 32, EE / 32),     dim3(32, 8)>>>(w_proj, wprojT, EE, EE);
    transpose_kernel<<<dim3(MLPD / 32, EE / 32),   dim3(32, 8)>>>(w_fc1, wfc1T, EE, MLPD);
    transpose_kernel<<<dim3(EE / 32, MLPD / 32),   dim3(32, 8)>>>(w_fc2, wfc2T, MLPD, EE);

    // 1. h = LN(x)
    ln_kernel<<<MR, 256>>>(x, g1, beta1, h);
    // 2. qkv = h @ w_qkv + b_qkv
    gemm_mma<0><<<dim3(3 * EE / 128, MR / 128), 256, GEMM_SMEM_BYTES>>>(
        h, wqkvT, b_qkv, nullptr, qkv, MR, 3 * EE, EE);
    // 3. attention
    attn_kernel<<<dim3(NN / 128, BB * HH), 128>>>(qkv, attn);
    // 4. x1 = attn @ w_proj + b_proj + x
    gemm_mma<2><<<dim3(EE / 128, MR / 128), 256, GEMM_SMEM_BYTES>>>(
        attn, wprojT, b_proj, x, x1, MR, EE, EE);
    // 5. h = LN(x1)
    ln_kernel<<<MR, 256>>>(x1, g2, beta2, h);
    // 6. mlp = gelu(h @ w_fc1 + b_fc1)
    gemm_mma<1><<<dim3(MLPD / 128, MR / 128), 256, GEMM_SMEM_BYTES>>>(
        h, wfc1T, b_fc1, nullptr, mlp, MR, MLPD, EE);
    // 7. out = mlp @ w_fc2 + b_fc2 + x1
    gemm_mma<2><<<dim3(EE / 128, MR / 128), 256, GEMM_SMEM_BYTES>>>(
        mlp, wfc2T, b_fc2, x1, out, MR, EE, MLPD);
}

// round 4
// speedup vs baseline: 2.8460x; 1.7754x over previous
#include <cuda_runtime.h>
#include <math.h>
#include <stdint.h>

// Problem constants
#define BB   2
#define NN   2048
#define EE   1024
#define HH   16
#define MLPD 4096
#define MR   (BB * NN)   // 4096 token rows

// ---------------- scratch (static device globals; no allocation) ----------------
__device__ float g_h[MR * EE];
__device__ float g_qkv[MR * 3 * EE];
__device__ float g_attn[MR * EE];
__device__ float g_x1[MR * EE];
__device__ float g_mlp[(size_t)MR * MLPD];
__device__ float g_wqkvT[3 * EE * EE];
__device__ float g_wprojT[EE * EE];
__device__ float g_wfc1T[(size_t)MLPD * EE];
__device__ float g_wfc2T[(size_t)EE * MLPD];

// ======================= helpers =================================
__device__ __forceinline__ uint32_t smem_u32(const void* p) {
    uint32_t a;
    asm("{ .reg .u64 t; cvta.to.shared.u64 t, %1; cvt.u32.u64 %0, t; }" : "=r"(a) : "l"(p));
    return a;
}
__device__ __forceinline__ float to_tf32(float x) {
    float r;
    asm("cvt.rna.tf32.f32 %0, %1;" : "=f"(r) : "f"(x));
    return r;
}
__device__ __forceinline__ float ex2(float x) {
    float r;
    asm("ex2.approx.ftz.f32 %0, %1;" : "=f"(r) : "f"(x));
    return r;
}
__device__ __forceinline__ void cp16(uint32_t dst, const void* src) {
    asm volatile("cp.async.cg.shared.global [%0], [%1], 16;" :: "r"(dst), "l"(src));
}
#define CP_COMMIT() asm volatile("cp.async.commit_group;" ::: "memory")
#define CP_WAIT1()  asm volatile("cp.async.wait_group 1;" ::: "memory")
#define CP_WAIT0()  asm volatile("cp.async.wait_group 0;" ::: "memory")

__device__ __forceinline__ void mma_tf32(float* c, const uint32_t* a, const uint32_t* b) {
    asm volatile(
        "mma.sync.aligned.m16n8k8.row.col.f32.tf32.tf32.f32 "
        "{%0,%1,%2,%3}, {%4,%5,%6,%7}, {%8,%9}, {%0,%1,%2,%3};"
        : "+f"(c[0]), "+f"(c[1]), "+f"(c[2]), "+f"(c[3])
        : "r"(a[0]), "r"(a[1]), "r"(a[2]), "r"(a[3]), "r"(b[0]), "r"(b[1]));
}

// ---------------- transpose: [R,C] -> [C,R], output rounded to tf32 -------------
__global__ void transpose_kernel(const float* __restrict__ in, float* __restrict__ out,
                                 int R, int C) {
    __shared__ float t[32][33];
    const int c = blockIdx.x * 32 + threadIdx.x;
    const int r0 = blockIdx.y * 32;
    #pragma unroll
    for (int i = threadIdx.y; i < 32; i += 8)
        t[i][threadIdx.x] = in[(size_t)(r0 + i) * C + c];
    __syncthreads();
    const int rc = blockIdx.y * 32 + threadIdx.x;
    const int c0 = blockIdx.x * 32;
    #pragma unroll
    for (int i = threadIdx.y; i < 32; i += 8)
        out[(size_t)(c0 + i) * R + rc] = to_tf32(t[threadIdx.x][i]);
}

// ---------------- LayerNorm, output rounded to tf32 -----------------------------
__global__ void ln_kernel(const float* __restrict__ x, const float* __restrict__ g,
                          const float* __restrict__ beta, float* __restrict__ out) {
    __shared__ float sh[8];
    const int row = blockIdx.x;
    const int tid = threadIdx.x;
    const float4 v = ((const float4*)(x + (size_t)row * EE))[tid];

    float s = v.x + v.y + v.z + v.w;
    #pragma unroll
    for (int o = 16; o; o >>= 1) s += __shfl_down_sync(0xffffffffu, s, o);
    if ((tid & 31) == 0) sh[tid >> 5] = s;
    __syncthreads();
    if (tid < 32) {
        float t = (tid < 8) ? sh[tid] : 0.f;
        #pragma unroll
        for (int o = 4; o; o >>= 1) t += __shfl_down_sync(0xffffffffu, t, o);
        if (tid == 0) sh[0] = t;
    }
    __syncthreads();
    const float mu = sh[0] * (1.0f / EE);
    __syncthreads();

    float dx = v.x - mu, dy = v.y - mu, dz = v.z - mu, dw = v.w - mu;
    float q = dx * dx + dy * dy + dz * dz + dw * dw;
    #pragma unroll
    for (int o = 16; o; o >>= 1) q += __shfl_down_sync(0xffffffffu, q, o);
    if ((tid & 31) == 0) sh[tid >> 5] = q;
    __syncthreads();
    if (tid < 32) {
        float t = (tid < 8) ? sh[tid] : 0.f;
        #pragma unroll
        for (int o = 4; o; o >>= 1) t += __shfl_down_sync(0xffffffffu, t, o);
        if (tid == 0) sh[0] = t;
    }
    __syncthreads();
    const float rstd = rsqrtf(sh[0] * (1.0f / EE) + 1e-5f);

    const float4 gv = ((const float4*)g)[tid];
    const float4 bv = ((const float4*)beta)[tid];
    float4 o;
    o.x = to_tf32(dx * rstd * gv.x + bv.x);
    o.y = to_tf32(dy * rstd * gv.y + bv.y);
    o.z = to_tf32(dz * rstd * gv.z + bv.z);
    o.w = to_tf32(dw * rstd * gv.w + bv.w);
    ((float4*)(out + (size_t)row * EE))[tid] = o;
}

// ---------------- tf32 mma.sync GEMM (unchanged from R3) ------------------------
#define ASTRIDE 36
#define STAGEF  (2 * 128 * ASTRIDE)
#define GEMM_SMEM_BYTES (2 * STAGEF * 4)

__device__ __forceinline__ void issue_tile(const float* __restrict__ A,
                                           const float* __restrict__ BT,
                                           float* sA, float* sB,
                                           int bm, int bn, int kc, int K, int tid) {
    #pragma unroll
    for (int p = 0; p < 4; p++) {
        const int e = p * 256 + tid;
        const int row = e >> 3, ch = e & 7;
        cp16(smem_u32(sA + row * ASTRIDE + ch * 4),
             A + (size_t)(bm + row) * K + kc * 32 + ch * 4);
        cp16(smem_u32(sB + row * ASTRIDE + ch * 4),
             BT + (size_t)(bn + row) * K + kc * 32 + ch * 4);
    }
}

template <int EPI>
__global__ __launch_bounds__(256, 1)
void gemm_mma(const float* __restrict__ A, const float* __restrict__ BT,
              const float* __restrict__ bias, const float* __restrict__ res,
              float* __restrict__ C, int M, int N, int K) {
    extern __shared__ __align__(16) float smem[];
    const int tid  = threadIdx.x;
    const int lane = tid & 31, warp = tid >> 5;
    const int wm = warp >> 2, wn = warp & 3;
    const int gq = lane >> 2, tq = lane & 3;
    const int bm = blockIdx.y << 7;
    const int bn = blockIdx.x << 7;
    const int NC = K >> 5;

    float* As[2] = { smem,          smem + STAGEF };
    float* Bs[2] = { smem + 128 * ASTRIDE, smem + STAGEF + 128 * ASTRIDE };

    float c[4][4][4];
    #pragma unroll
    for (int i = 0; i < 4; i++)
        #pragma unroll
        for (int j = 0; j < 4; j++)
            #pragma unroll
            for (int k = 0; k < 4; k++) c[i][j][k] = 0.f;

    issue_tile(A, BT, As[0], Bs[0], bm, bn, 0, K, tid); CP_COMMIT();
    issue_tile(A, BT, As[1], Bs[1], bm, bn, 1, K, tid); CP_COMMIT();

    for (int kc = 0; kc < NC; kc++) {
        const int b = kc & 1;
        CP_WAIT1();
        __syncthreads();
        const float* sa = As[b] + (wm * 64 + gq) * ASTRIDE;
        const float* sb = Bs[b] + (wn * 32 + gq) * ASTRIDE;
        #pragma unroll
        for (int ks = 0; ks < 4; ks++) {
            uint32_t af[4][4], bf[4][2];
            #pragma unroll
            for (int mt = 0; mt < 4; mt++) {
                const float* ap = sa + mt * 16 * ASTRIDE + ks * 8 + tq;
                af[mt][0] = __float_as_uint(ap[0]);
                af[mt][1] = __float_as_uint(ap[8 * ASTRIDE]);
                af[mt][2] = __float_as_uint(ap[4]);
                af[mt][3] = __float_as_uint(ap[8 * ASTRIDE + 4]);
            }
            #pragma unroll
            for (int nt = 0; nt < 4; nt++) {
                const float* bp = sb + nt * 8 * ASTRIDE + ks * 8 + tq;
                bf[nt][0] = __float_as_uint(bp[0]);
                bf[nt][1] = __float_as_uint(bp[4]);
            }
            #pragma unroll
            for (int mt = 0; mt < 4; mt++)
                #pragma unroll
                for (int nt = 0; nt < 4; nt++)
                    mma_tf32(c[mt][nt], af[mt], bf[nt]);
        }
        __syncthreads();
        if (kc + 2 < NC) issue_tile(A, BT, As[b], Bs[b], bm, bn, kc + 2, K, tid);
        CP_COMMIT();
    }

    #pragma unroll
    for (int mt = 0; mt < 4; mt++) {
        const int row0 = bm + wm * 64 + mt * 16 + gq;
        #pragma unroll
        for (int nt = 0; nt < 4; nt++) {
            const int col = bn + wn * 32 + nt * 8 + 2 * tq;
            const float bx = bias[col], by = bias[col + 1];
            #pragma unroll
            for (int half = 0; half < 2; half++) {
                const int row = row0 + half * 8;
                float vx = c[mt][nt][half * 2 + 0] + bx;
                float vy = c[mt][nt][half * 2 + 1] + by;
                if (EPI == 1) {
                    vx = 0.5f * vx * (1.0f + erff(vx * 0.70710678118654752f));
                    vy = 0.5f * vy * (1.0f + erff(vy * 0.70710678118654752f));
                    vx = to_tf32(vx); vy = to_tf32(vy);
                }
                if (EPI == 2) {
                    const float2 rv = *(const float2*)(res + (size_t)row * N + col);
                    vx += rv.x; vy += rv.y;
                }
                float2 o; o.x = vx; o.y = vy;
                *(float2*)(C + (size_t)row * N + col) = o;
            }
        }
    }
}

// ---------------- Flash attention, tf32 mma.sync --------------------------------
// CTA: 128 queries x one (b,h). 8 warps x 16 query rows. Key tiles of 64.
// Zero-shuffle P reuse: S C-frag cols {2tq,2tq+1} feed PV A-frag directly; V
// B-frag compensates by reading smem key rows 2tq / 2tq+1 (column permutation,
// softmax-invariant).
#define KVS 68   // smem row stride (floats), conflict-free for both frag patterns

__global__ __launch_bounds__(256, 1)
void attn_mma(const float* __restrict__ qkv, float* __restrict__ out) {
    __shared__ float Ks[64 * KVS];
    __shared__ float Vs[64 * KVS];
    const int tid  = threadIdx.x;
    const int lane = tid & 31, warp = tid >> 5;
    const int gq = lane >> 2, tq = lane & 3;
    const int bh = blockIdx.y;
    const int b = bh >> 4, h = bh & 15;
    const int q0 = blockIdx.x * 128;

    // ---- Q fragments (persistent), pre-scaled by D^-0.5 * log2(e) ----
    const float qscale = 0.125f * 1.4426950408889634f;
    float aq[8][4];
    {
        const float* r0 = qkv + (size_t)(b * NN + q0 + warp * 16 + gq) * 3072 + h * 64;
        const float* r1 = r0 + (size_t)8 * 3072;
        #pragma unroll
        for (int ks = 0; ks < 8; ks++) {
            aq[ks][0] = to_tf32(r0[ks * 8 + tq] * qscale);
            aq[ks][1] = to_tf32(r1[ks * 8 + tq] * qscale);
            aq[ks][2] = to_tf32(r0[ks * 8 + tq + 4] * qscale);
            aq[ks][3] = to_tf32(r1[ks * 8 + tq + 4] * qscale);
        }
    }

    float oc[8][4];
    #pragma unroll
    for (int i = 0; i < 8; i++)
        #pragma unroll
        for (int j = 0; j < 4; j++) oc[i][j] = 0.f;
    float m0 = -1e30f, m1 = -1e30f, l0 = 0.f, l1 = 0.f;

    for (int kt = 0; kt < NN / 64; kt++) {
        const int k0 = kt * 64;
        // ---- load K,V tiles (64 keys x 64 d) via cp.async ----
        #pragma unroll
        for (int it = 0; it < 4; it++) {
            const int e = it * 256 + tid;
            const int row = e >> 4, ch = e & 15;
            const size_t gbase = (size_t)(b * NN + k0 + row) * 3072 + h * 64 + ch * 4;
            cp16(smem_u32(Ks + row * KVS + ch * 4), qkv + gbase + 1024);
            cp16(smem_u32(Vs + row * KVS + ch * 4), qkv + gbase + 2048);
        }
        CP_COMMIT();
        CP_WAIT0();
        __syncthreads();

        // ---- S = Q K^T (scaled, log2 domain) ----
        float sc[8][4];
        #pragma unroll
        for (int i = 0; i < 8; i++)
            #pragma unroll
            for (int j = 0; j < 4; j++) sc[i][j] = 0.f;
        #pragma unroll
        for (int ks = 0; ks < 8; ks++) {
            uint32_t a[4] = { __float_as_uint(aq[ks][0]), __float_as_uint(aq[ks][1]),
                              __float_as_uint(aq[ks][2]), __float_as_uint(aq[ks][3]) };
            #pragma unroll
            for (int nt = 0; nt < 8; nt++) {
                const float* kp = Ks + (nt * 8 + gq) * KVS + ks * 8 + tq;
                uint32_t bfr[2] = { __float_as_uint(kp[0]), __float_as_uint(kp[4]) };
                mma_tf32(sc[nt], a, bfr);
            }
        }

        // ---- online softmax (exp2 domain) ----
        float mx0 = -1e30f, mx1 = -1e30f;
        #pragma unroll
        for (int nt = 0; nt < 8; nt++) {
            mx0 = fmaxf(mx0, fmaxf(sc[nt][0], sc[nt][1]));
            mx1 = fmaxf(mx1, fmaxf(sc[nt][2], sc[nt][3]));
        }
        mx0 = fmaxf(mx0, __shfl_xor_sync(0xffffffffu, mx0, 1));
        mx0 = fmaxf(mx0, __shfl_xor_sync(0xffffffffu, mx0, 2));
        mx1 = fmaxf(mx1, __shfl_xor_sync(0xffffffffu, mx1, 1));
        mx1 = fmaxf(mx1, __shfl_xor_sync(0xffffffffu, mx1, 2));
        const float mn0 = fmaxf(m0, mx0), mn1 = fmaxf(m1, mx1);
        const float f0 = ex2(m0 - mn0), f1 = ex2(m1 - mn1);
        m0 = mn0; m1 = mn1;
        l0 *= f0; l1 *= f1;
        #pragma unroll
        for (int dt = 0; dt < 8; dt++) {
            oc[dt][0] *= f0; oc[dt][1] *= f0;
            oc[dt][2] *= f1; oc[dt][3] *= f1;
        }

        // ---- P = exp2(S - m); PV accumulate ----
        #pragma unroll
        for (int nt = 0; nt < 8; nt++) {
            const float p0 = ex2(sc[nt][0] - m0);
            const float p1 = ex2(sc[nt][1] - m0);
            const float p2 = ex2(sc[nt][2] - m1);
            const float p3 = ex2(sc[nt][3] - m1);
            l0 += p0 + p1; l1 += p2 + p3;
            uint32_t pa[4] = { __float_as_uint(to_tf32(p0)), __float_as_uint(to_tf32(p2)),
                               __float_as_uint(to_tf32(p1)), __float_as_uint(to_tf32(p3)) };
            const float* vp = Vs + (nt * 8 + 2 * tq) * KVS;
            #pragma unroll
            for (int dt = 0; dt < 8; dt++) {
                uint32_t bfr[2] = { __float_as_uint(vp[dt * 8 + gq]),
                                    __float_as_uint(vp[KVS + dt * 8 + gq]) };
                mma_tf32(oc[dt], pa, bfr);
            }
        }
        __syncthreads();
    }

    // ---- finalize ----
    l0 += __shfl_xor_sync(0xffffffffu, l0, 1);
    l0 += __shfl_xor_sync(0xffffffffu, l0, 2);
    l1 += __shfl_xor_sync(0xffffffffu, l1, 1);
    l1 += __shfl_xor_sync(0xffffffffu, l1, 2);
    const float inv0 = 1.f / l0, inv1 = 1.f / l1;
    const int row0 = b * NN + q0 + warp * 16 + gq;
    float* o0 = out + (size_t)row0 * EE + h * 64;
    float* o1 = o0 + (size_t)8 * EE;
    #pragma unroll
    for (int dt = 0; dt < 8; dt++) {
        float2 v0, v1;
        v0.x = to_tf32(oc[dt][0] * inv0); v0.y = to_tf32(oc[dt][1] * inv0);
        v1.x = to_tf32(oc[dt][2] * inv1); v1.y = to_tf32(oc[dt][3] * inv1);
        *(float2*)(o0 + dt * 8 + 2 * tq) = v0;
        *(float2*)(o1 + dt * 8 + 2 * tq) = v1;
    }
}

// ---------------- host launch ---------------------------------------------------
extern "C" void kernel_launch(void* const* d_in, const int* in_sizes, int n_in,
                              void* d_out, int out_size) {
    const float* x      = (const float*)d_in[0];
    const float* w_qkv  = (const float*)d_in[1];
    const float* b_qkv  = (const float*)d_in[2];
    const float* w_proj = (const float*)d_in[3];
    const float* b_proj = (const float*)d_in[4];
    const float* g1     = (const float*)d_in[5];
    const float* beta1  = (const float*)d_in[6];
    const float* g2     = (const float*)d_in[7];
    const float* beta2  = (const float*)d_in[8];
    const float* w_fc1  = (const float*)d_in[9];
    const float* b_fc1  = (const float*)d_in[10];
    const float* w_fc2  = (const float*)d_in[11];
    const float* b_fc2  = (const float*)d_in[12];
    float* out = (float*)d_out;

    float *h, *qkv, *attn, *x1, *mlp, *wqkvT, *wprojT, *wfc1T, *wfc2T;
    cudaGetSymbolAddress((void**)&h,      g_h);
    cudaGetSymbolAddress((void**)&qkv,    g_qkv);
    cudaGetSymbolAddress((void**)&attn,   g_attn);
    cudaGetSymbolAddress((void**)&x1,     g_x1);
    cudaGetSymbolAddress((void**)&mlp,    g_mlp);
    cudaGetSymbolAddress((void**)&wqkvT,  g_wqkvT);
    cudaGetSymbolAddress((void**)&wprojT, g_wprojT);
    cudaGetSymbolAddress((void**)&wfc1T,  g_wfc1T);
    cudaGetSymbolAddress((void**)&wfc2T,  g_wfc2T);

    cudaFuncSetAttribute(gemm_mma<0>, cudaFuncAttributeMaxDynamicSharedMemorySize, GEMM_SMEM_BYTES);
    cudaFuncSetAttribute(gemm_mma<1>, cudaFuncAttributeMaxDynamicSharedMemorySize, GEMM_SMEM_BYTES);
    cudaFuncSetAttribute(gemm_mma<2>, cudaFuncAttributeMaxDynamicSharedMemorySize, GEMM_SMEM_BYTES);

    transpose_kernel<<<dim3(3 * EE / 32, EE / 32), dim3(32, 8)>>>(w_qkv, wqkvT, EE, 3 * EE);
    transpose_kernel<<<dim3(EE / 32, EE / 32),     dim3(32, 8)>>>(w_proj, wprojT, EE, EE);
    transpose_kernel<<<dim3(MLPD / 32, EE / 32),   dim3(32, 8)>>>(w_fc1, wfc1T, EE, MLPD);
    transpose_kernel<<<dim3(EE / 32, MLPD / 32),   dim3(32, 8)>>>(w_fc2, wfc2T, MLPD, EE);

    ln_kernel<<<MR, 256>>>(x, g1, beta1, h);
    gemm_mma<0><<<dim3(3 * EE / 128, MR / 128), 256, GEMM_SMEM_BYTES>>>(
        h, wqkvT, b_qkv, nullptr, qkv, MR, 3 * EE, EE);
    attn_mma<<<dim3(NN / 128, BB * HH), 256>>>(qkv, attn);
    gemm_mma<2><<<dim3(EE / 128, MR / 128), 256, GEMM_SMEM_BYTES>>>(
        attn, wprojT, b_proj, x, x1, MR, EE, EE);
    ln_kernel<<<MR, 256>>>(x1, g2, beta2, h);
    gemm_mma<1><<<dim3(MLPD / 128, MR / 128), 256, GEMM_SMEM_BYTES>>>(
        h, wfc1T, b_fc1, nullptr, mlp, MR, MLPD, EE);
    gemm_mma<2><<<dim3(EE / 128, MR / 128), 256, GEMM_SMEM_BYTES>>>(
        mlp, wfc2T, b_fc2, x1, out, MR, EE, MLPD);
}

// round 5
// speedup vs baseline: 3.6252x; 1.2738x over previous
#include <cuda_runtime.h>
#include <math.h>
#include <stdint.h>

// Problem constants
#define BB   2
#define NN   2048
#define EE   1024
#define HH   16
#define MLPD 4096
#define MR   (BB * NN)   // 4096 token rows

// ---------------- scratch (static device globals; no allocation) ----------------
__device__ float g_h[MR * EE];
__device__ float g_qkv[MR * 3 * EE];
__device__ float g_attn[MR * EE];
__device__ float g_x1[MR * EE];
__device__ float g_mlp[(size_t)MR * MLPD];
__device__ float g_wqkvT[3 * EE * EE];
__device__ float g_wprojT[EE * EE];
__device__ float g_wfc1T[(size_t)MLPD * EE];
__device__ float g_wfc2T[(size_t)EE * MLPD];

// ======================= helpers =================================
__device__ __forceinline__ uint32_t smem_u32(const void* p) {
    uint32_t a;
    asm("{ .reg .u64 t; cvta.to.shared.u64 t, %1; cvt.u32.u64 %0, t; }" : "=r"(a) : "l"(p));
    return a;
}
__device__ __forceinline__ float to_tf32(float x) {
    float r;
    asm("cvt.rna.tf32.f32 %0, %1;" : "=f"(r) : "f"(x));
    return r;
}
__device__ __forceinline__ float ex2(float x) {
    float r;
    asm("ex2.approx.ftz.f32 %0, %1;" : "=f"(r) : "f"(x));
    return r;
}
__device__ __forceinline__ void cp16(uint32_t dst, const void* src) {
    asm volatile("cp.async.cg.shared.global [%0], [%1], 16;" :: "r"(dst), "l"(src));
}
#define CP_COMMIT() asm volatile("cp.async.commit_group;" ::: "memory")
#define CP_WAIT1()  asm volatile("cp.async.wait_group 1;" ::: "memory")

__device__ __forceinline__ void mma_tf32(float* c, const uint32_t* a, const uint32_t* b) {
    asm volatile(
        "mma.sync.aligned.m16n8k8.row.col.f32.tf32.tf32.f32 "
        "{%0,%1,%2,%3}, {%4,%5,%6,%7}, {%8,%9}, {%0,%1,%2,%3};"
        : "+f"(c[0]), "+f"(c[1]), "+f"(c[2]), "+f"(c[3])
        : "r"(a[0]), "r"(a[1]), "r"(a[2]), "r"(a[3]), "r"(b[0]), "r"(b[1]));
}

// ---------------- transpose: [R,C] -> [C,R], output rounded to tf32 -------------
__global__ void transpose_kernel(const float* __restrict__ in, float* __restrict__ out,
                                 int R, int C) {
    __shared__ float t[32][33];
    const int c = blockIdx.x * 32 + threadIdx.x;
    const int r0 = blockIdx.y * 32;
    #pragma unroll
    for (int i = threadIdx.y; i < 32; i += 8)
        t[i][threadIdx.x] = in[(size_t)(r0 + i) * C + c];
    __syncthreads();
    const int rc = blockIdx.y * 32 + threadIdx.x;
    const int c0 = blockIdx.x * 32;
    #pragma unroll
    for (int i = threadIdx.y; i < 32; i += 8)
        out[(size_t)(c0 + i) * R + rc] = to_tf32(t[threadIdx.x][i]);
}

// ---------------- LayerNorm, output rounded to tf32 -----------------------------
__global__ void ln_kernel(const float* __restrict__ x, const float* __restrict__ g,
                          const float* __restrict__ beta, float* __restrict__ out) {
    __shared__ float sh[8];
    const int row = blockIdx.x;
    const int tid = threadIdx.x;
    const float4 v = ((const float4*)(x + (size_t)row * EE))[tid];

    float s = v.x + v.y + v.z + v.w;
    #pragma unroll
    for (int o = 16; o; o >>= 1) s += __shfl_down_sync(0xffffffffu, s, o);
    if ((tid & 31) == 0) sh[tid >> 5] = s;
    __syncthreads();
    if (tid < 32) {
        float t = (tid < 8) ? sh[tid] : 0.f;
        #pragma unroll
        for (int o = 4; o; o >>= 1) t += __shfl_down_sync(0xffffffffu, t, o);
        if (tid == 0) sh[0] = t;
    }
    __syncthreads();
    const float mu = sh[0] * (1.0f / EE);
    __syncthreads();

    float dx = v.x - mu, dy = v.y - mu, dz = v.z - mu, dw = v.w - mu;
    float q = dx * dx + dy * dy + dz * dz + dw * dw;
    #pragma unroll
    for (int o = 16; o; o >>= 1) q += __shfl_down_sync(0xffffffffu, q, o);
    if ((tid & 31) == 0) sh[tid >> 5] = q;
    __syncthreads();
    if (tid < 32) {
        float t = (tid < 8) ? sh[tid] : 0.f;
        #pragma unroll
        for (int o = 4; o; o >>= 1) t += __shfl_down_sync(0xffffffffu, t, o);
        if (tid == 0) sh[0] = t;
    }
    __syncthreads();
    const float rstd = rsqrtf(sh[0] * (1.0f / EE) + 1e-5f);

    const float4 gv = ((const float4*)g)[tid];
    const float4 bv = ((const float4*)beta)[tid];
    float4 o;
    o.x = to_tf32(dx * rstd * gv.x + bv.x);
    o.y = to_tf32(dy * rstd * gv.y + bv.y);
    o.z = to_tf32(dz * rstd * gv.z + bv.z);
    o.w = to_tf32(dw * rstd * gv.w + bv.w);
    ((float4*)(out + (size_t)row * EE))[tid] = o;
}

// ---------------- tf32 mma.sync GEMM: CTA 128x256, 3-stage, 1 barrier/chunk -----
#define ASTR 36
#define STG  ((128 + 256) * ASTR)            // floats per stage
#define GEMM_SMEM_BYTES (3 * STG * 4)        // 165888 bytes

__device__ __forceinline__ void issue_tile(const float* __restrict__ A,
                                           const float* __restrict__ BT,
                                           float* stage, int bm, int bn,
                                           int kc, int K, int tid) {
    float* sA = stage;
    float* sB = stage + 128 * ASTR;
    #pragma unroll
    for (int p = 0; p < 4; p++) {
        const int e = p * 256 + tid;
        const int row = e >> 3, ch = e & 7;
        cp16(smem_u32(sA + row * ASTR + ch * 4),
             A + (size_t)(bm + row) * K + kc * 32 + ch * 4);
    }
    #pragma unroll
    for (int p = 0; p < 8; p++) {
        const int e = p * 256 + tid;
        const int row = e >> 3, ch = e & 7;
        cp16(smem_u32(sB + row * ASTR + ch * 4),
             BT + (size_t)(bn + row) * K + kc * 32 + ch * 4);
    }
}

template <int EPI>
__global__ __launch_bounds__(256, 1)
void gemm_mma(const float* __restrict__ A, const float* __restrict__ BT,
              const float* __restrict__ bias, const float* __restrict__ res,
              float* __restrict__ C, int M, int N, int K) {
    extern __shared__ __align__(16) float smem[];
    const int tid  = threadIdx.x;
    const int lane = tid & 31, warp = tid >> 5;
    const int wm = warp >> 2, wn = warp & 3;     // 2 x 4 warps, 64x64 tiles
    const int gq = lane >> 2, tq = lane & 3;
    const int bm = blockIdx.y << 7;
    const int bn = blockIdx.x << 8;
    const int NC = K >> 5;

    float c[4][8][4];
    #pragma unroll
    for (int i = 0; i < 4; i++)
        #pragma unroll
        for (int j = 0; j < 8; j++)
            #pragma unroll
            for (int k = 0; k < 4; k++) c[i][j][k] = 0.f;

    issue_tile(A, BT, smem,       bm, bn, 0, K, tid); CP_COMMIT();
    issue_tile(A, BT, smem + STG, bm, bn, 1, K, tid); CP_COMMIT();

    int st = 0;  // stage of chunk kc
    for (int kc = 0; kc < NC; kc++) {
        CP_WAIT1();               // chunk kc resident
        __syncthreads();          // all warps done with stage being refilled
        if (kc + 2 < NC) {
            int nst = st + 2; if (nst >= 3) nst -= 3;
            issue_tile(A, BT, smem + nst * STG, bm, bn, kc + 2, K, tid);
        }
        CP_COMMIT();
        const float* sa = smem + st * STG + (wm * 64 + gq) * ASTR;
        const float* sb = smem + st * STG + 128 * ASTR + (wn * 64 + gq) * ASTR;
        #pragma unroll
        for (int ks = 0; ks < 4; ks++) {
            uint32_t af[4][4], bf[8][2];
            #pragma unroll
            for (int mt = 0; mt < 4; mt++) {
                const float* ap = sa + mt * 16 * ASTR + ks * 8 + tq;
                af[mt][0] = __float_as_uint(ap[0]);
                af[mt][1] = __float_as_uint(ap[8 * ASTR]);
                af[mt][2] = __float_as_uint(ap[4]);
                af[mt][3] = __float_as_uint(ap[8 * ASTR + 4]);
            }
            #pragma unroll
            for (int nt = 0; nt < 8; nt++) {
                const float* bp = sb + nt * 8 * ASTR + ks * 8 + tq;
                bf[nt][0] = __float_as_uint(bp[0]);
                bf[nt][1] = __float_as_uint(bp[4]);
            }
            #pragma unroll
            for (int mt = 0; mt < 4; mt++)
                #pragma unroll
                for (int nt = 0; nt < 8; nt++)
                    mma_tf32(c[mt][nt], af[mt], bf[nt]);
        }
        if (++st >= 3) st = 0;
    }

    // ---- epilogue ----
    #pragma unroll
    for (int mt = 0; mt < 4; mt++) {
        const int row0 = bm + wm * 64 + mt * 16 + gq;
        #pragma unroll
        for (int nt = 0; nt < 8; nt++) {
            const int col = bn + wn * 64 + nt * 8 + 2 * tq;
            const float bx = bias[col], by = bias[col + 1];
            #pragma unroll
            for (int half = 0; half < 2; half++) {
                const int row = row0 + half * 8;
                float vx = c[mt][nt][half * 2 + 0] + bx;
                float vy = c[mt][nt][half * 2 + 1] + by;
                if (EPI == 1) {
                    vx = 0.5f * vx * (1.0f + erff(vx * 0.70710678118654752f));
                    vy = 0.5f * vy * (1.0f + erff(vy * 0.70710678118654752f));
                    vx = to_tf32(vx); vy = to_tf32(vy);
                }
                if (EPI == 2) {
                    const float2 rv = *(const float2*)(res + (size_t)row * N + col);
                    vx += rv.x; vy += rv.y;
                }
                float2 o; o.x = vx; o.y = vy;
                *(float2*)(C + (size_t)row * N + col) = o;
            }
        }
    }
}

// ---------------- Flash attention, tf32 mma.sync, double-buffered K/V -----------
#define KVS 68   // smem row stride (floats), conflict-free for both frag patterns
#define ATTN_SMEM_BYTES (2 * 2 * 64 * KVS * 4)   // 139264 bytes

__global__ __launch_bounds__(256, 1)
void attn_mma(const float* __restrict__ qkv, float* __restrict__ out) {
    extern __shared__ __align__(16) float asmem[];
    const int tid  = threadIdx.x;
    const int lane = tid & 31, warp = tid >> 5;
    const int gq = lane >> 2, tq = lane & 3;
    const int bh = blockIdx.y;
    const int b = bh >> 4, h = bh & 15;
    const int q0 = blockIdx.x * 128;

    // buffers: [buf][K/V][64*KVS]
    float* Kbuf[2] = { asmem,                asmem + 2 * 64 * KVS };
    float* Vbuf[2] = { asmem + 64 * KVS,     asmem + 3 * 64 * KVS };

    // ---- Q fragments (persistent), pre-scaled by D^-0.5 * log2(e) ----
    const float qscale = 0.125f * 1.4426950408889634f;
    float aq[8][4];
    {
        const float* r0 = qkv + (size_t)(b * NN + q0 + warp * 16 + gq) * 3072 + h * 64;
        const float* r1 = r0 + (size_t)8 * 3072;
        #pragma unroll
        for (int ks = 0; ks < 8; ks++) {
            aq[ks][0] = to_tf32(r0[ks * 8 + tq] * qscale);
            aq[ks][1] = to_tf32(r1[ks * 8 + tq] * qscale);
            aq[ks][2] = to_tf32(r0[ks * 8 + tq + 4] * qscale);
            aq[ks][3] = to_tf32(r1[ks * 8 + tq + 4] * qscale);
        }
    }

    float oc[8][4];
    #pragma unroll
    for (int i = 0; i < 8; i++)
        #pragma unroll
        for (int j = 0; j < 4; j++) oc[i][j] = 0.f;
    float m0 = -1e30f, m1 = -1e30f, l0 = 0.f, l1 = 0.f;

    // tile loader
    auto issue_kv = [&](int buf, int kt) {
        #pragma unroll
        for (int it = 0; it < 4; it++) {
            const int e = it * 256 + tid;
            const int row = e >> 4, ch = e & 15;
            const size_t gbase = (size_t)(b * NN + kt * 64 + row) * 3072 + h * 64 + ch * 4;
            cp16(smem_u32(Kbuf[buf] + row * KVS + ch * 4), qkv + gbase + 1024);
            cp16(smem_u32(Vbuf[buf] + row * KVS + ch * 4), qkv + gbase + 2048);
        }
    };

    issue_kv(0, 0); CP_COMMIT();

    for (int kt = 0; kt < NN / 64; kt++) {
        const int cb = kt & 1;
        issue_kv(cb ^ 1, (kt + 1) & (NN / 64 - 1));   // prefetch next (wraps, harmless)
        CP_COMMIT();
        CP_WAIT1();                                   // current tile resident
        __syncthreads();
        const float* Ks = Kbuf[cb];
        const float* Vs = Vbuf[cb];

        // ---- S = Q K^T (scaled, log2 domain) ----
        float sc[8][4];
        #pragma unroll
        for (int i = 0; i < 8; i++)
            #pragma unroll
            for (int j = 0; j < 4; j++) sc[i][j] = 0.f;
        #pragma unroll
        for (int ks = 0; ks < 8; ks++) {
            uint32_t a[4] = { __float_as_uint(aq[ks][0]), __float_as_uint(aq[ks][1]),
                              __float_as_uint(aq[ks][2]), __float_as_uint(aq[ks][3]) };
            #pragma unroll
            for (int nt = 0; nt < 8; nt++) {
                const float* kp = Ks + (nt * 8 + gq) * KVS + ks * 8 + tq;
                uint32_t bfr[2] = { __float_as_uint(kp[0]), __float_as_uint(kp[4]) };
                mma_tf32(sc[nt], a, bfr);
            }
        }

        // ---- online softmax (exp2 domain) ----
        float mx0 = -1e30f, mx1 = -1e30f;
        #pragma unroll
        for (int nt = 0; nt < 8; nt++) {
            mx0 = fmaxf(mx0, fmaxf(sc[nt][0], sc[nt][1]));
            mx1 = fmaxf(mx1, fmaxf(sc[nt][2], sc[nt][3]));
        }
        mx0 = fmaxf(mx0, __shfl_xor_sync(0xffffffffu, mx0, 1));
        mx0 = fmaxf(mx0, __shfl_xor_sync(0xffffffffu, mx0, 2));
        mx1 = fmaxf(mx1, __shfl_xor_sync(0xffffffffu, mx1, 1));
        mx1 = fmaxf(mx1, __shfl_xor_sync(0xffffffffu, mx1, 2));
        const float mn0 = fmaxf(m0, mx0), mn1 = fmaxf(m1, mx1);
        const float f0 = ex2(m0 - mn0), f1 = ex2(m1 - mn1);
        m0 = mn0; m1 = mn1;
        l0 *= f0; l1 *= f1;
        #pragma unroll
        for (int dt = 0; dt < 8; dt++) {
            oc[dt][0] *= f0; oc[dt][1] *= f0;
            oc[dt][2] *= f1; oc[dt][3] *= f1;
        }

        // ---- P = exp2(S - m); PV accumulate ----
        #pragma unroll
        for (int nt = 0; nt < 8; nt++) {
            const float p0 = ex2(sc[nt][0] - m0);
            const float p1 = ex2(sc[nt][1] - m0);
            const float p2 = ex2(sc[nt][2] - m1);
            const float p3 = ex2(sc[nt][3] - m1);
            l0 += p0 + p1; l1 += p2 + p3;
            uint32_t pa[4] = { __float_as_uint(to_tf32(p0)), __float_as_uint(to_tf32(p2)),
                               __float_as_uint(to_tf32(p1)), __float_as_uint(to_tf32(p3)) };
            const float* vp = Vs + (nt * 8 + 2 * tq) * KVS;
            #pragma unroll
            for (int dt = 0; dt < 8; dt++) {
                uint32_t bfr[2] = { __float_as_uint(vp[dt * 8 + gq]),
                                    __float_as_uint(vp[KVS + dt * 8 + gq]) };
                mma_tf32(oc[dt], pa, bfr);
            }
        }
        __syncthreads();
    }

    // ---- finalize ----
    l0 += __shfl_xor_sync(0xffffffffu, l0, 1);
    l0 += __shfl_xor_sync(0xffffffffu, l0, 2);
    l1 += __shfl_xor_sync(0xffffffffu, l1, 1);
    l1 += __shfl_xor_sync(0xffffffffu, l1, 2);
    const float inv0 = 1.f / l0, inv1 = 1.f / l1;
    const int row0 = b * NN + q0 + warp * 16 + gq;
    float* o0 = out + (size_t)row0 * EE + h * 64;
    float* o1 = o0 + (size_t)8 * EE;
    #pragma unroll
    for (int dt = 0; dt < 8; dt++) {
        float2 v0, v1;
        v0.x = to_tf32(oc[dt][0] * inv0); v0.y = to_tf32(oc[dt][1] * inv0);
        v1.x = to_tf32(oc[dt][2] * inv1); v1.y = to_tf32(oc[dt][3] * inv1);
        *(float2*)(o0 + dt * 8 + 2 * tq) = v0;
        *(float2*)(o1 + dt * 8 + 2 * tq) = v1;
    }
}

// ---------------- host launch ---------------------------------------------------
extern "C" void kernel_launch(void* const* d_in, const int* in_sizes, int n_in,
                              void* d_out, int out_size) {
    const float* x      = (const float*)d_in[0];
    const float* w_qkv  = (const float*)d_in[1];
    const float* b_qkv  = (const float*)d_in[2];
    const float* w_proj = (const float*)d_in[3];
    const float* b_proj = (const float*)d_in[4];
    const float* g1     = (const float*)d_in[5];
    const float* beta1  = (const float*)d_in[6];
    const float* g2     = (const float*)d_in[7];
    const float* beta2  = (const float*)d_in[8];
    const float* w_fc1  = (const float*)d_in[9];
    const float* b_fc1  = (const float*)d_in[10];
    const float* w_fc2  = (const float*)d_in[11];
    const float* b_fc2  = (const float*)d_in[12];
    float* out = (float*)d_out;

    float *h, *qkv, *attn, *x1, *mlp, *wqkvT, *wprojT, *wfc1T, *wfc2T;
    cudaGetSymbolAddress((void**)&h,      g_h);
    cudaGetSymbolAddress((void**)&qkv,    g_qkv);
    cudaGetSymbolAddress((void**)&attn,   g_attn);
    cudaGetSymbolAddress((void**)&x1,     g_x1);
    cudaGetSymbolAddress((void**)&mlp,    g_mlp);
    cudaGetSymbolAddress((void**)&wqkvT,  g_wqkvT);
    cudaGetSymbolAddress((void**)&wprojT, g_wprojT);
    cudaGetSymbolAddress((void**)&wfc1T,  g_wfc1T);
    cudaGetSymbolAddress((void**)&wfc2T,  g_wfc2T);

    cudaFuncSetAttribute(gemm_mma<0>, cudaFuncAttributeMaxDynamicSharedMemorySize, GEMM_SMEM_BYTES);
    cudaFuncSetAttribute(gemm_mma<1>, cudaFuncAttributeMaxDynamicSharedMemorySize, GEMM_SMEM_BYTES);
    cudaFuncSetAttribute(gemm_mma<2>, cudaFuncAttributeMaxDynamicSharedMemorySize, GEMM_SMEM_BYTES);
    cudaFuncSetAttribute(attn_mma,    cudaFuncAttributeMaxDynamicSharedMemorySize, ATTN_SMEM_BYTES);

    transpose_kernel<<<dim3(3 * EE / 32, EE / 32), dim3(32, 8)>>>(w_qkv, wqkvT, EE, 3 * EE);
    transpose_kernel<<<dim3(EE / 32, EE / 32),     dim3(32, 8)>>>(w_proj, wprojT, EE, EE);
    transpose_kernel<<<dim3(MLPD / 32, EE / 32),   dim3(32, 8)>>>(w_fc1, wfc1T, EE, MLPD);
    transpose_kernel<<<dim3(EE / 32, MLPD / 32),   dim3(32, 8)>>>(w_fc2, wfc2T, MLPD, EE);

    ln_kernel<<<MR, 256>>>(x, g1, beta1, h);
    gemm_mma<0><<<dim3(3 * EE / 256, MR / 128), 256, GEMM_SMEM_BYTES>>>(
        h, wqkvT, b_qkv, nullptr, qkv, MR, 3 * EE, EE);
    attn_mma<<<dim3(NN / 128, BB * HH), 256, ATTN_SMEM_BYTES>>>(qkv, attn);
    gemm_mma<2><<<dim3(EE / 256, MR / 128), 256, GEMM_SMEM_BYTES>>>(
        attn, wprojT, b_proj, x, x1, MR, EE, EE);
    ln_kernel<<<MR, 256>>>(x1, g2, beta2, h);
    gemm_mma<1><<<dim3(MLPD / 256, MR / 128), 256, GEMM_SMEM_BYTES>>>(
        h, wfc1T, b_fc1, nullptr, mlp, MR, MLPD, EE);
    gemm_mma<2><<<dim3(EE / 256, MR / 128), 256, GEMM_SMEM_BYTES>>>(
        mlp, wfc2T, b_fc2, x1, out, MR, EE, MLPD);
}

// round 6
// speedup vs baseline: 6.6964x; 1.8472x over previous
#include <cuda_runtime.h>
#include <cuda_bf16.h>
#include <math.h>
#include <stdint.h>

// Problem constants
#define BB   2
#define NN   2048
#define EE   1024
#define HH   16
#define MLPD 4096
#define MR   (BB * NN)   // 4096 token rows

// ---------------- scratch (static device globals; no allocation) ----------------
__device__ __nv_bfloat16 g_h[MR * EE];               // LN output (bf16)
__device__ __nv_bfloat16 g_qkv[MR * 3 * EE];         // QKV (bf16)
__device__ __nv_bfloat16 g_attn[MR * EE];            // attention out (bf16)
__device__ float         g_x1[MR * EE];              // residual 1 (fp32)
__device__ __nv_bfloat16 g_mlp[(size_t)MR * MLPD];   // GELU(fc1) (bf16)
__device__ __nv_bfloat16 g_wqkvT[3 * EE * EE];       // transposed weights [N,K] bf16
__device__ __nv_bfloat16 g_wprojT[EE * EE];
__device__ __nv_bfloat16 g_wfc1T[(size_t)MLPD * EE];
__device__ __nv_bfloat16 g_wfc2T[(size_t)EE * MLPD];

// ======================= helpers =================================
__device__ __forceinline__ uint32_t smem_u32(const void* p) {
    uint32_t a;
    asm("{ .reg .u64 t; cvta.to.shared.u64 t, %1; cvt.u32.u64 %0, t; }" : "=r"(a) : "l"(p));
    return a;
}
__device__ __forceinline__ float ex2(float x) {
    float r;
    asm("ex2.approx.ftz.f32 %0, %1;" : "=f"(r) : "f"(x));
    return r;
}
__device__ __forceinline__ uint32_t pack_bf16(float lo, float hi) {
    uint32_t r;
    asm("cvt.rn.bf16x2.f32 %0, %1, %2;" : "=r"(r) : "f"(hi), "f"(lo));
    return r;
}
__device__ __forceinline__ void cp16(uint32_t dst, const void* src) {
    asm volatile("cp.async.cg.shared.global [%0], [%1], 16;" :: "r"(dst), "l"(src));
}
#define CP_COMMIT() asm volatile("cp.async.commit_group;" ::: "memory")
#define CP_WAIT1()  asm volatile("cp.async.wait_group 1;" ::: "memory")

__device__ __forceinline__ void mma_bf16(float* c, const uint32_t* a, const uint32_t* b) {
    asm volatile(
        "mma.sync.aligned.m16n8k16.row.col.f32.bf16.bf16.f32 "
        "{%0,%1,%2,%3}, {%4,%5,%6,%7}, {%8,%9}, {%0,%1,%2,%3};"
        : "+f"(c[0]), "+f"(c[1]), "+f"(c[2]), "+f"(c[3])
        : "r"(a[0]), "r"(a[1]), "r"(a[2]), "r"(a[3]), "r"(b[0]), "r"(b[1]));
}
__device__ __forceinline__ void ldsm_x4(uint32_t* r, uint32_t addr) {
    asm volatile("ldmatrix.sync.aligned.m8n8.x4.shared.b16 {%0,%1,%2,%3}, [%4];"
                 : "=r"(r[0]), "=r"(r[1]), "=r"(r[2]), "=r"(r[3]) : "r"(addr));
}
__device__ __forceinline__ void ldsm_x2(uint32_t* r, uint32_t addr) {
    asm volatile("ldmatrix.sync.aligned.m8n8.x2.shared.b16 {%0,%1}, [%2];"
                 : "=r"(r[0]), "=r"(r[1]) : "r"(addr));
}
__device__ __forceinline__ void ldsm_x2t(uint32_t* r, uint32_t addr) {
    asm volatile("ldmatrix.sync.aligned.m8n8.x2.trans.shared.b16 {%0,%1}, [%2];"
                 : "=r"(r[0]), "=r"(r[1]) : "r"(addr));
}

// ---------------- transpose: [R,C] fp32 -> [C,R] bf16 ---------------------------
__global__ void transpose_kernel(const float* __restrict__ in,
                                 __nv_bfloat16* __restrict__ out, int R, int C) {
    __shared__ float t[32][33];
    const int c = blockIdx.x * 32 + threadIdx.x;
    const int r0 = blockIdx.y * 32;
    #pragma unroll
    for (int i = threadIdx.y; i < 32; i += 8)
        t[i][threadIdx.x] = in[(size_t)(r0 + i) * C + c];
    __syncthreads();
    const int rc = blockIdx.y * 32 + threadIdx.x;
    const int c0 = blockIdx.x * 32;
    #pragma unroll
    for (int i = threadIdx.y; i < 32; i += 8)
        out[(size_t)(c0 + i) * R + rc] = __float2bfloat16_rn(t[threadIdx.x][i]);
}

// ---------------- LayerNorm fp32 -> bf16 -----------------------------------------
__global__ void ln_kernel(const float* __restrict__ x, const float* __restrict__ g,
                          const float* __restrict__ beta,
                          __nv_bfloat16* __restrict__ out) {
    __shared__ float sh[8];
    const int row = blockIdx.x;
    const int tid = threadIdx.x;
    const float4 v = ((const float4*)(x + (size_t)row * EE))[tid];

    float s = v.x + v.y + v.z + v.w;
    #pragma unroll
    for (int o = 16; o; o >>= 1) s += __shfl_down_sync(0xffffffffu, s, o);
    if ((tid & 31) == 0) sh[tid >> 5] = s;
    __syncthreads();
    if (tid < 32) {
        float t = (tid < 8) ? sh[tid] : 0.f;
        #pragma unroll
        for (int o = 4; o; o >>= 1) t += __shfl_down_sync(0xffffffffu, t, o);
        if (tid == 0) sh[0] = t;
    }
    __syncthreads();
    const float mu = sh[0] * (1.0f / EE);
    __syncthreads();

    float dx = v.x - mu, dy = v.y - mu, dz = v.z - mu, dw = v.w - mu;
    float q = dx * dx + dy * dy + dz * dz + dw * dw;
    #pragma unroll
    for (int o = 16; o; o >>= 1) q += __shfl_down_sync(0xffffffffu, q, o);
    if ((tid & 31) == 0) sh[tid >> 5] = q;
    __syncthreads();
    if (tid < 32) {
        float t = (tid < 8) ? sh[tid] : 0.f;
        #pragma unroll
        for (int o = 4; o; o >>= 1) t += __shfl_down_sync(0xffffffffu, t, o);
        if (tid == 0) sh[0] = t;
    }
    __syncthreads();
    const float rstd = rsqrtf(sh[0] * (1.0f / EE) + 1e-5f);

    const float4 gv = ((const float4*)g)[tid];
    const float4 bv = ((const float4*)beta)[tid];
    uint2 o;
    o.x = pack_bf16(dx * rstd * gv.x + bv.x, dy * rstd * gv.y + bv.y);
    o.y = pack_bf16(dz * rstd * gv.z + bv.z, dw * rstd * gv.w + bv.w);
    ((uint2*)(out + (size_t)row * EE))[tid] = o;
}

// ---------------- bf16 mma.sync GEMM: CTA 128x256, 3-stage, ldmatrix -------------
// C[M,N] = A[M,K] @ BT[N,K]^T + bias; EPI: 0=none(bf16 out), 1=GELU(bf16 out),
// 2=+res (fp32 out). K-chunk 64 (bf16), 4 k16 steps per chunk.
#define ASTR 72                                    // bf16 row stride, conflict-free
#define STG  ((128 + 256) * ASTR)                  // bf16 per stage
#define GEMM_SMEM_BYTES (3 * STG * 2)              // 165888 bytes

__device__ __forceinline__ void issue_tile(const __nv_bfloat16* __restrict__ A,
                                           const __nv_bfloat16* __restrict__ BT,
                                           __nv_bfloat16* stage, int bm, int bn,
                                           int kc, int K, int tid) {
    __nv_bfloat16* sA = stage;
    __nv_bfloat16* sB = stage + 128 * ASTR;
    #pragma unroll
    for (int p = 0; p < 4; p++) {
        const int e = p * 256 + tid;
        const int row = e >> 3, ch = e & 7;
        cp16(smem_u32(sA + row * ASTR + ch * 8),
             A + (size_t)(bm + row) * K + kc * 64 + ch * 8);
    }
    #pragma unroll
    for (int p = 0; p < 8; p++) {
        const int e = p * 256 + tid;
        const int row = e >> 3, ch = e & 7;
        cp16(smem_u32(sB + row * ASTR + ch * 8),
             BT + (size_t)(bn + row) * K + kc * 64 + ch * 8);
    }
}

template <int EPI>
__global__ __launch_bounds__(256, 1)
void gemm_mma(const __nv_bfloat16* __restrict__ A, const __nv_bfloat16* __restrict__ BT,
              const float* __restrict__ bias, const float* __restrict__ res,
              void* __restrict__ Cout, int M, int N, int K) {
    extern __shared__ __align__(16) __nv_bfloat16 smem[];
    const int tid  = threadIdx.x;
    const int lane = tid & 31, warp = tid >> 5;
    const int wm = warp >> 2, wn = warp & 3;     // 2 x 4 warps, 64x64 warp tiles
    const int gq = lane >> 2, tq = lane & 3;
    const int l15 = lane & 15;
    const int arow = l15, asel = lane >> 4;      // A ldmatrix x4 addressing
    const int rrow = l15 & 7, rsel = l15 >> 3;   // B ldmatrix x2 addressing
    const int bm = blockIdx.y << 7;
    const int bn = blockIdx.x << 8;
    const int NC = K >> 6;

    float c[4][8][4];
    #pragma unroll
    for (int i = 0; i < 4; i++)
        #pragma unroll
        for (int j = 0; j < 8; j++)
            #pragma unroll
            for (int k = 0; k < 4; k++) c[i][j][k] = 0.f;

    issue_tile(A, BT, smem,       bm, bn, 0, K, tid); CP_COMMIT();
    issue_tile(A, BT, smem + STG, bm, bn, 1, K, tid); CP_COMMIT();

    int st = 0;
    for (int kc = 0; kc < NC; kc++) {
        CP_WAIT1();
        __syncthreads();
        if (kc + 2 < NC) {
            int nst = st + 2; if (nst >= 3) nst -= 3;
            issue_tile(A, BT, smem + nst * STG, bm, bn, kc + 2, K, tid);
        }
        CP_COMMIT();
        const __nv_bfloat16* sa = smem + st * STG + (size_t)(wm * 64) * ASTR;
        const __nv_bfloat16* sb = smem + st * STG + (size_t)128 * ASTR + (size_t)(wn * 64) * ASTR;
        #pragma unroll
        for (int ks = 0; ks < 4; ks++) {
            uint32_t af[4][4], bf[8][2];
            #pragma unroll
            for (int mt = 0; mt < 4; mt++)
                ldsm_x4(af[mt], smem_u32(sa + (mt * 16 + arow) * ASTR + ks * 16 + asel * 8));
            #pragma unroll
            for (int nt = 0; nt < 8; nt++)
                ldsm_x2(bf[nt], smem_u32(sb + (nt * 8 + rrow) * ASTR + ks * 16 + rsel * 8));
            #pragma unroll
            for (int mt = 0; mt < 4; mt++)
                #pragma unroll
                for (int nt = 0; nt < 8; nt++)
                    mma_bf16(c[mt][nt], af[mt], bf[nt]);
        }
        if (++st >= 3) st = 0;
    }

    // ---- epilogue ----
    #pragma unroll
    for (int mt = 0; mt < 4; mt++) {
        const int row0 = bm + wm * 64 + mt * 16 + gq;
        #pragma unroll
        for (int nt = 0; nt < 8; nt++) {
            const int col = bn + wn * 64 + nt * 8 + 2 * tq;
            const float bx = bias[col], by = bias[col + 1];
            #pragma unroll
            for (int half = 0; half < 2; half++) {
                const int row = row0 + half * 8;
                float vx = c[mt][nt][half * 2 + 0] + bx;
                float vy = c[mt][nt][half * 2 + 1] + by;
                if (EPI == 1) {
                    vx = 0.5f * vx * (1.0f + erff(vx * 0.70710678118654752f));
                    vy = 0.5f * vy * (1.0f + erff(vy * 0.70710678118654752f));
                }
                if (EPI == 2) {
                    const float2 rv = *(const float2*)(res + (size_t)row * N + col);
                    float2 o; o.x = vx + rv.x; o.y = vy + rv.y;
                    *(float2*)((float*)Cout + (size_t)row * N + col) = o;
                } else {
                    *(uint32_t*)((__nv_bfloat16*)Cout + (size_t)row * N + col) =
                        pack_bf16(vx, vy);
                }
            }
        }
    }
}

// ---------------- Flash attention, bf16 mma.sync ---------------------------------
// CTA: 128 queries x one (b,h). 8 warps x 16 query rows. Key tiles of 64,
// double-buffered. P C-frag feeds PV A-frag via bf16x2 pack (no shuffle, no
// permutation). V consumed via ldmatrix.trans.
#define KVS 72   // bf16 row stride, conflict-free for ldmatrix patterns

__global__ __launch_bounds__(256, 1)
void attn_mma(const __nv_bfloat16* __restrict__ qkv, __nv_bfloat16* __restrict__ out) {
    __shared__ __nv_bfloat16 Kb[2][64 * KVS];
    __shared__ __nv_bfloat16 Vb[2][64 * KVS];
    const int tid  = threadIdx.x;
    const int lane = tid & 31, warp = tid >> 5;
    const int gq = lane >> 2, tq = lane & 3;
    const int l15 = lane & 15;
    const int rrow = l15 & 7, rsel = l15 >> 3;
    const int bh = blockIdx.y;
    const int b = bh >> 4, h = bh & 15;
    const int q0 = blockIdx.x * 128;

    // ---- Q fragments: direct bf16x2 gmem loads (4 k16 steps over D=64) ----
    uint32_t aq[4][4];
    {
        const __nv_bfloat16* r0 = qkv + (size_t)(b * NN + q0 + warp * 16 + gq) * 3072 + h * 64;
        const __nv_bfloat16* r1 = r0 + (size_t)8 * 3072;
        #pragma unroll
        for (int ks = 0; ks < 4; ks++) {
            aq[ks][0] = *(const uint32_t*)(r0 + ks * 16 + 2 * tq);
            aq[ks][1] = *(const uint32_t*)(r1 + ks * 16 + 2 * tq);
            aq[ks][2] = *(const uint32_t*)(r0 + ks * 16 + 2 * tq + 8);
            aq[ks][3] = *(const uint32_t*)(r1 + ks * 16 + 2 * tq + 8);
        }
    }

    float oc[8][4];
    #pragma unroll
    for (int i = 0; i < 8; i++)
        #pragma unroll
        for (int j = 0; j < 4; j++) oc[i][j] = 0.f;
    float m0 = -1e30f, m1 = -1e30f, l0 = 0.f, l1 = 0.f;
    const float qsc = 0.125f * 1.4426950408889634f;  // D^-0.5 * log2(e)

    auto issue_kv = [&](int buf, int kt) {
        #pragma unroll
        for (int it = 0; it < 2; it++) {
            const int e = it * 256 + tid;
            const int row = e >> 3, ch = e & 7;
            const size_t gbase = (size_t)(b * NN + kt * 64 + row) * 3072 + h * 64 + ch * 8;
            cp16(smem_u32(&Kb[buf][row * KVS + ch * 8]), qkv + gbase + 1024);
            cp16(smem_u32(&Vb[buf][row * KVS + ch * 8]), qkv + gbase + 2048);
        }
    };

    issue_kv(0, 0); CP_COMMIT();

    for (int kt = 0; kt < NN / 64; kt++) {
        const int cb = kt & 1;
        issue_kv(cb ^ 1, (kt + 1) & (NN / 64 - 1));
        CP_COMMIT();
        CP_WAIT1();
        __syncthreads();
        const __nv_bfloat16* Ks = Kb[cb];
        const __nv_bfloat16* Vs = Vb[cb];

        // ---- S = Q K^T ----
        float sc[8][4];
        #pragma unroll
        for (int i = 0; i < 8; i++)
            #pragma unroll
            for (int j = 0; j < 4; j++) sc[i][j] = 0.f;
        #pragma unroll
        for (int ks = 0; ks < 4; ks++) {
            #pragma unroll
            for (int nt = 0; nt < 8; nt++) {
                uint32_t bfr[2];
                ldsm_x2(bfr, smem_u32(Ks + (nt * 8 + rrow) * KVS + ks * 16 + rsel * 8));
                mma_bf16(sc[nt], aq[ks], bfr);
            }
        }
        #pragma unroll
        for (int nt = 0; nt < 8; nt++) {
            sc[nt][0] *= qsc; sc[nt][1] *= qsc; sc[nt][2] *= qsc; sc[nt][3] *= qsc;
        }

        // ---- online softmax (exp2 domain) ----
        float mx0 = -1e30f, mx1 = -1e30f;
        #pragma unroll
        for (int nt = 0; nt < 8; nt++) {
            mx0 = fmaxf(mx0, fmaxf(sc[nt][0], sc[nt][1]));
            mx1 = fmaxf(mx1, fmaxf(sc[nt][2], sc[nt][3]));
        }
        mx0 = fmaxf(mx0, __shfl_xor_sync(0xffffffffu, mx0, 1));
        mx0 = fmaxf(mx0, __shfl_xor_sync(0xffffffffu, mx0, 2));
        mx1 = fmaxf(mx1, __shfl_xor_sync(0xffffffffu, mx1, 1));
        mx1 = fmaxf(mx1, __shfl_xor_sync(0xffffffffu, mx1, 2));
        const float mn0 = fmaxf(m0, mx0), mn1 = fmaxf(m1, mx1);
        const float f0 = ex2(m0 - mn0), f1 = ex2(m1 - mn1);
        m0 = mn0; m1 = mn1;
        l0 *= f0; l1 *= f1;
        #pragma unroll
        for (int dt = 0; dt < 8; dt++) {
            oc[dt][0] *= f0; oc[dt][1] *= f0;
            oc[dt][2] *= f1; oc[dt][3] *= f1;
        }

        // ---- P = exp2(S - m); PV accumulate (4 k16 steps over 64 keys) ----
        #pragma unroll
        for (int j = 0; j < 4; j++) {
            const int t0 = 2 * j, t1 = 2 * j + 1;
            const float p00 = ex2(sc[t0][0] - m0), p01 = ex2(sc[t0][1] - m0);
            const float p02 = ex2(sc[t0][2] - m1), p03 = ex2(sc[t0][3] - m1);
            const float p10 = ex2(sc[t1][0] - m0), p11 = ex2(sc[t1][1] - m0);
            const float p12 = ex2(sc[t1][2] - m1), p13 = ex2(sc[t1][3] - m1);
            l0 += p00 + p01 + p10 + p11;
            l1 += p02 + p03 + p12 + p13;
            uint32_t pa[4] = { pack_bf16(p00, p01), pack_bf16(p02, p03),
                               pack_bf16(p10, p11), pack_bf16(p12, p13) };
            #pragma unroll
            for (int dt = 0; dt < 8; dt++) {
                uint32_t bfr[2];
                ldsm_x2t(bfr, smem_u32(Vs + (16 * j + l15) * KVS + dt * 8));
                mma_bf16(oc[dt], pa, bfr);
            }
        }
        __syncthreads();
    }

    // ---- finalize ----
    l0 += __shfl_xor_sync(0xffffffffu, l0, 1);
    l0 += __shfl_xor_sync(0xffffffffu, l0, 2);
    l1 += __shfl_xor_sync(0xffffffffu, l1, 1);
    l1 += __shfl_xor_sync(0xffffffffu, l1, 2);
    const float inv0 = 1.f / l0, inv1 = 1.f / l1;
    const int row0 = b * NN + q0 + warp * 16 + gq;
    __nv_bfloat16* o0 = out + (size_t)row0 * EE + h * 64;
    __nv_bfloat16* o1 = o0 + (size_t)8 * EE;
    #pragma unroll
    for (int dt = 0; dt < 8; dt++) {
        *(uint32_t*)(o0 + dt * 8 + 2 * tq) = pack_bf16(oc[dt][0] * inv0, oc[dt][1] * inv0);
        *(uint32_t*)(o1 + dt * 8 + 2 * tq) = pack_bf16(oc[dt][2] * inv1, oc[dt][3] * inv1);
    }
}

// ---------------- host launch ---------------------------------------------------
extern "C" void kernel_launch(void* const* d_in, const int* in_sizes, int n_in,
                              void* d_out, int out_size) {
    const float* x      = (const float*)d_in[0];
    const float* w_qkv  = (const float*)d_in[1];
    const float* b_qkv  = (const float*)d_in[2];
    const float* w_proj = (const float*)d_in[3];
    const float* b_proj = (const float*)d_in[4];
    const float* g1     = (const float*)d_in[5];
    const float* beta1  = (const float*)d_in[6];
    const float* g2     = (const float*)d_in[7];
    const float* beta2  = (const float*)d_in[8];
    const float* w_fc1  = (const float*)d_in[9];
    const float* b_fc1  = (const float*)d_in[10];
    const float* w_fc2  = (const float*)d_in[11];
    const float* b_fc2  = (const float*)d_in[12];
    float* out = (float*)d_out;

    __nv_bfloat16 *h, *qkv, *attn, *mlp, *wqkvT, *wprojT, *wfc1T, *wfc2T;
    float* x1;
    cudaGetSymbolAddress((void**)&h,      g_h);
    cudaGetSymbolAddress((void**)&qkv,    g_qkv);
    cudaGetSymbolAddress((void**)&attn,   g_attn);
    cudaGetSymbolAddress((void**)&x1,     g_x1);
    cudaGetSymbolAddress((void**)&mlp,    g_mlp);
    cudaGetSymbolAddress((void**)&wqkvT,  g_wqkvT);
    cudaGetSymbolAddress((void**)&wprojT, g_wprojT);
    cudaGetSymbolAddress((void**)&wfc1T,  g_wfc1T);
    cudaGetSymbolAddress((void**)&wfc2T,  g_wfc2T);

    cudaFuncSetAttribute(gemm_mma<0>, cudaFuncAttributeMaxDynamicSharedMemorySize, GEMM_SMEM_BYTES);
    cudaFuncSetAttribute(gemm_mma<1>, cudaFuncAttributeMaxDynamicSharedMemorySize, GEMM_SMEM_BYTES);
    cudaFuncSetAttribute(gemm_mma<2>, cudaFuncAttributeMaxDynamicSharedMemorySize, GEMM_SMEM_BYTES);

    transpose_kernel<<<dim3(3 * EE / 32, EE / 32), dim3(32, 8)>>>(w_qkv, wqkvT, EE, 3 * EE);
    transpose_kernel<<<dim3(EE / 32, EE / 32),     dim3(32, 8)>>>(w_proj, wprojT, EE, EE);
    transpose_kernel<<<dim3(MLPD / 32, EE / 32),   dim3(32, 8)>>>(w_fc1, wfc1T, EE, MLPD);
    transpose_kernel<<<dim3(EE / 32, MLPD / 32),   dim3(32, 8)>>>(w_fc2, wfc2T, MLPD, EE);

    // 1. h = LN(x) -> bf16
    ln_kernel<<<MR, 256>>>(x, g1, beta1, h);
    // 2. qkv = h @ w_qkv + b_qkv -> bf16
    gemm_mma<0><<<dim3(3 * EE / 256, MR / 128), 256, GEMM_SMEM_BYTES>>>(
        h, wqkvT, b_qkv, nullptr, qkv, MR, 3 * EE, EE);
    // 3. attention -> bf16
    attn_mma<<<dim3(NN / 128, BB * HH), 256>>>(qkv, attn);
    // 4. x1 = attn @ w_proj + b_proj + x -> fp32
    gemm_mma<2><<<dim3(EE / 256, MR / 128), 256, GEMM_SMEM_BYTES>>>(
        attn, wprojT, b_proj, x, x1, MR, EE, EE);
    // 5. h = LN(x1) -> bf16
    ln_kernel<<<MR, 256>>>(x1, g2, beta2, h);
    // 6. mlp = gelu(h @ w_fc1 + b_fc1) -> bf16
    gemm_mma<1><<<dim3(MLPD / 256, MR / 128), 256, GEMM_SMEM_BYTES>>>(
        h, wfc1T, b_fc1, nullptr, mlp, MR, MLPD, EE);
    // 7. out = mlp @ w_fc2 + b_fc2 + x1 -> fp32
    gemm_mma<2><<<dim3(EE / 256, MR / 128), 256, GEMM_SMEM_BYTES>>>(
        mlp, wfc2T, b_fc2, x1, out, MR, EE, MLPD);
}

// round 7
// speedup vs baseline: 6.9131x; 1.0324x over previous
#include <cuda_runtime.h>
#include <cuda_bf16.h>
#include <math.h>
#include <stdint.h>

// Problem constants
#define BB   2
#define NN   2048
#define EE   1024
#define HH   16
#define MLPD 4096
#define MR   (BB * NN)   // 4096 token rows

// ---------------- scratch (static device globals; no allocation) ----------------
__device__ __nv_bfloat16 g_h[MR * EE];               // LN output (bf16)
__device__ __nv_bfloat16 g_qkv[MR * 3 * EE];         // QKV (bf16)
__device__ __nv_bfloat16 g_attn[MR * EE];            // attention out (bf16)
__device__ float         g_x1[MR * EE];              // residual 1 (fp32)
__device__ __nv_bfloat16 g_mlp[(size_t)MR * MLPD];   // GELU(fc1) (bf16)
__device__ __nv_bfloat16 g_wqkvT[3 * EE * EE];       // transposed weights [N,K] bf16
__device__ __nv_bfloat16 g_wprojT[EE * EE];
__device__ __nv_bfloat16 g_wfc1T[(size_t)MLPD * EE];
__device__ __nv_bfloat16 g_wfc2T[(size_t)EE * MLPD];

// ======================= helpers =================================
__device__ __forceinline__ uint32_t smem_u32(const void* p) {
    uint32_t a;
    asm("{ .reg .u64 t; cvta.to.shared.u64 t, %1; cvt.u32.u64 %0, t; }" : "=r"(a) : "l"(p));
    return a;
}
__device__ __forceinline__ float ex2(float x) {
    float r;
    asm("ex2.approx.ftz.f32 %0, %1;" : "=f"(r) : "f"(x));
    return r;
}
__device__ __forceinline__ uint32_t pack_bf16(float lo, float hi) {
    uint32_t r;
    asm("cvt.rn.bf16x2.f32 %0, %1, %2;" : "=r"(r) : "f"(hi), "f"(lo));
    return r;
}
__device__ __forceinline__ void cp16(uint32_t dst, const void* src) {
    asm volatile("cp.async.cg.shared.global [%0], [%1], 16;" :: "r"(dst), "l"(src));
}
#define CP_COMMIT() asm volatile("cp.async.commit_group;" ::: "memory")
#define CP_WAIT1()  asm volatile("cp.async.wait_group 1;" ::: "memory")

__device__ __forceinline__ void mma_bf16(float* c, const uint32_t* a, const uint32_t* b) {
    asm volatile(
        "mma.sync.aligned.m16n8k16.row.col.f32.bf16.bf16.f32 "
        "{%0,%1,%2,%3}, {%4,%5,%6,%7}, {%8,%9}, {%0,%1,%2,%3};"
        : "+f"(c[0]), "+f"(c[1]), "+f"(c[2]), "+f"(c[3])
        : "r"(a[0]), "r"(a[1]), "r"(a[2]), "r"(a[3]), "r"(b[0]), "r"(b[1]));
}
__device__ __forceinline__ void ldsm_x4(uint32_t* r, uint32_t addr) {
    asm volatile("ldmatrix.sync.aligned.m8n8.x4.shared.b16 {%0,%1,%2,%3}, [%4];"
                 : "=r"(r[0]), "=r"(r[1]), "=r"(r[2]), "=r"(r[3]) : "r"(addr));
}
__device__ __forceinline__ void ldsm_x2(uint32_t* r, uint32_t addr) {
    asm volatile("ldmatrix.sync.aligned.m8n8.x2.shared.b16 {%0,%1}, [%2];"
                 : "=r"(r[0]), "=r"(r[1]) : "r"(addr));
}
__device__ __forceinline__ void ldsm_x2t(uint32_t* r, uint32_t addr) {
    asm volatile("ldmatrix.sync.aligned.m8n8.x2.trans.shared.b16 {%0,%1}, [%2];"
                 : "=r"(r[0]), "=r"(r[1]) : "r"(addr));
}

// ---------------- fused transpose of all 4 weights: one launch -------------------
// tiles: qkv 96x32=3072, proj 32x32=1024, fc1 128x32=4096, fc2 32x128=4096
#define T_QKV  3072
#define T_PROJ (T_QKV + 1024)
#define T_FC1  (T_PROJ + 4096)
#define T_FC2  (T_FC1 + 4096)

__global__ void transpose_all(const float* __restrict__ w0, const float* __restrict__ w1,
                              const float* __restrict__ w2, const float* __restrict__ w3,
                              __nv_bfloat16* __restrict__ o0, __nv_bfloat16* __restrict__ o1,
                              __nv_bfloat16* __restrict__ o2, __nv_bfloat16* __restrict__ o3) {
    __shared__ float t[32][33];
    int tt = blockIdx.x;
    const float* in;
    __nv_bfloat16* out;
    int R, C;
    if (tt < T_QKV)       { in = w0; out = o0; R = EE;   C = 3 * EE; }
    else if (tt < T_PROJ) { in = w1; out = o1; R = EE;   C = EE;   tt -= T_QKV;  }
    else if (tt < T_FC1)  { in = w2; out = o2; R = EE;   C = MLPD; tt -= T_PROJ; }
    else                  { in = w3; out = o3; R = MLPD; C = EE;   tt -= T_FC1;  }
    const int ctiles = C >> 5;
    const int bx = tt % ctiles, by = tt / ctiles;

    const int c = bx * 32 + threadIdx.x;
    const int r0 = by * 32;
    #pragma unroll
    for (int i = threadIdx.y; i < 32; i += 8)
        t[i][threadIdx.x] = in[(size_t)(r0 + i) * C + c];
    __syncthreads();
    const int rc = by * 32 + threadIdx.x;
    const int c0 = bx * 32;
    #pragma unroll
    for (int i = threadIdx.y; i < 32; i += 8)
        out[(size_t)(c0 + i) * R + rc] = __float2bfloat16_rn(t[threadIdx.x][i]);
}

// ---------------- LayerNorm fp32 -> bf16 -----------------------------------------
__global__ void ln_kernel(const float* __restrict__ x, const float* __restrict__ g,
                          const float* __restrict__ beta,
                          __nv_bfloat16* __restrict__ out) {
    __shared__ float sh[8];
    const int row = blockIdx.x;
    const int tid = threadIdx.x;
    const float4 v = ((const float4*)(x + (size_t)row * EE))[tid];

    float s = v.x + v.y + v.z + v.w;
    #pragma unroll
    for (int o = 16; o; o >>= 1) s += __shfl_down_sync(0xffffffffu, s, o);
    if ((tid & 31) == 0) sh[tid >> 5] = s;
    __syncthreads();
    if (tid < 32) {
        float t = (tid < 8) ? sh[tid] : 0.f;
        #pragma unroll
        for (int o = 4; o; o >>= 1) t += __shfl_down_sync(0xffffffffu, t, o);
        if (tid == 0) sh[0] = t;
    }
    __syncthreads();
    const float mu = sh[0] * (1.0f / EE);
    __syncthreads();

    float dx = v.x - mu, dy = v.y - mu, dz = v.z - mu, dw = v.w - mu;
    float q = dx * dx + dy * dy + dz * dz + dw * dw;
    #pragma unroll
    for (int o = 16; o; o >>= 1) q += __shfl_down_sync(0xffffffffu, q, o);
    if ((tid & 31) == 0) sh[tid >> 5] = q;
    __syncthreads();
    if (tid < 32) {
        float t = (tid < 8) ? sh[tid] : 0.f;
        #pragma unroll
        for (int o = 4; o; o >>= 1) t += __shfl_down_sync(0xffffffffu, t, o);
        if (tid == 0) sh[0] = t;
    }
    __syncthreads();
    const float rstd = rsqrtf(sh[0] * (1.0f / EE) + 1e-5f);

    const float4 gv = ((const float4*)g)[tid];
    const float4 bv = ((const float4*)beta)[tid];
    uint2 o;
    o.x = pack_bf16(dx * rstd * gv.x + bv.x, dy * rstd * gv.y + bv.y);
    o.y = pack_bf16(dz * rstd * gv.z + bv.z, dw * rstd * gv.w + bv.w);
    ((uint2*)(out + (size_t)row * EE))[tid] = o;
}

// ---------------- bf16 mma.sync GEMM: CTA 128x256, 3-stage, ldmatrix -------------
#define ASTR 72
#define STG  ((128 + 256) * ASTR)
#define GEMM_SMEM_BYTES (3 * STG * 2)

__device__ __forceinline__ void issue_tile(const __nv_bfloat16* __restrict__ A,
                                           const __nv_bfloat16* __restrict__ BT,
                                           __nv_bfloat16* stage, int bm, int bn,
                                           int kc, int K, int tid) {
    __nv_bfloat16* sA = stage;
    __nv_bfloat16* sB = stage + 128 * ASTR;
    #pragma unroll
    for (int p = 0; p < 4; p++) {
        const int e = p * 256 + tid;
        const int row = e >> 3, ch = e & 7;
        cp16(smem_u32(sA + row * ASTR + ch * 8),
             A + (size_t)(bm + row) * K + kc * 64 + ch * 8);
    }
    #pragma unroll
    for (int p = 0; p < 8; p++) {
        const int e = p * 256 + tid;
        const int row = e >> 3, ch = e & 7;
        cp16(smem_u32(sB + row * ASTR + ch * 8),
             BT + (size_t)(bn + row) * K + kc * 64 + ch * 8);
    }
}

template <int EPI>
__global__ __launch_bounds__(256, 1)
void gemm_mma(const __nv_bfloat16* __restrict__ A, const __nv_bfloat16* __restrict__ BT,
              const float* __restrict__ bias, const float* __restrict__ res,
              void* __restrict__ Cout, int M, int N, int K) {
    extern __shared__ __align__(16) __nv_bfloat16 smem[];
    const int tid  = threadIdx.x;
    const int lane = tid & 31, warp = tid >> 5;
    const int wm = warp >> 2, wn = warp & 3;
    const int gq = lane >> 2, tq = lane & 3;
    const int l15 = lane & 15;
    const int arow = l15, asel = lane >> 4;
    const int rrow = l15 & 7, rsel = l15 >> 3;
    const int bm = blockIdx.y << 7;
    const int bn = blockIdx.x << 8;
    const int NC = K >> 6;

    float c[4][8][4];
    #pragma unroll
    for (int i = 0; i < 4; i++)
        #pragma unroll
        for (int j = 0; j < 8; j++)
            #pragma unroll
            for (int k = 0; k < 4; k++) c[i][j][k] = 0.f;

    issue_tile(A, BT, smem,       bm, bn, 0, K, tid); CP_COMMIT();
    issue_tile(A, BT, smem + STG, bm, bn, 1, K, tid); CP_COMMIT();

    int st = 0;
    for (int kc = 0; kc < NC; kc++) {
        CP_WAIT1();
        __syncthreads();
        if (kc + 2 < NC) {
            int nst = st + 2; if (nst >= 3) nst -= 3;
            issue_tile(A, BT, smem + nst * STG, bm, bn, kc + 2, K, tid);
        }
        CP_COMMIT();
        const __nv_bfloat16* sa = smem + st * STG + (size_t)(wm * 64) * ASTR;
        const __nv_bfloat16* sb = smem + st * STG + (size_t)128 * ASTR + (size_t)(wn * 64) * ASTR;
        #pragma unroll
        for (int ks = 0; ks < 4; ks++) {
            uint32_t af[4][4], bf[8][2];
            #pragma unroll
            for (int mt = 0; mt < 4; mt++)
                ldsm_x4(af[mt], smem_u32(sa + (mt * 16 + arow) * ASTR + ks * 16 + asel * 8));
            #pragma unroll
            for (int nt = 0; nt < 8; nt++)
                ldsm_x2(bf[nt], smem_u32(sb + (nt * 8 + rrow) * ASTR + ks * 16 + rsel * 8));
            #pragma unroll
            for (int mt = 0; mt < 4; mt++)
                #pragma unroll
                for (int nt = 0; nt < 8; nt++)
                    mma_bf16(c[mt][nt], af[mt], bf[nt]);
        }
        if (++st >= 3) st = 0;
    }

    // ---- epilogue ----
    #pragma unroll
    for (int mt = 0; mt < 4; mt++) {
        const int row0 = bm + wm * 64 + mt * 16 + gq;
        #pragma unroll
        for (int nt = 0; nt < 8; nt++) {
            const int col = bn + wn * 64 + nt * 8 + 2 * tq;
            const float bx = bias[col], by = bias[col + 1];
            #pragma unroll
            for (int half = 0; half < 2; half++) {
                const int row = row0 + half * 8;
                float vx = c[mt][nt][half * 2 + 0] + bx;
                float vy = c[mt][nt][half * 2 + 1] + by;
                if (EPI == 1) {
                    vx = 0.5f * vx * (1.0f + erff(vx * 0.70710678118654752f));
                    vy = 0.5f * vy * (1.0f + erff(vy * 0.70710678118654752f));
                }
                if (EPI == 2) {
                    const float2 rv = *(const float2*)(res + (size_t)row * N + col);
                    float2 o; o.x = vx + rv.x; o.y = vy + rv.y;
                    *(float2*)((float*)Cout + (size_t)row * N + col) = o;
                } else {
                    *(uint32_t*)((__nv_bfloat16*)Cout + (size_t)row * N + col) =
                        pack_bf16(vx, vy);
                }
            }
        }
    }
}

// ---------------- Flash attention, bf16 mma.sync, occupancy 2 --------------------
#define KVS 72

__global__ __launch_bounds__(256, 2)
void attn_mma(const __nv_bfloat16* __restrict__ qkv, __nv_bfloat16* __restrict__ out) {
    __shared__ __nv_bfloat16 Kb[2][64 * KVS];
    __shared__ __nv_bfloat16 Vb[2][64 * KVS];
    const int tid  = threadIdx.x;
    const int lane = tid & 31, warp = tid >> 5;
    const int gq = lane >> 2, tq = lane & 3;
    const int l15 = lane & 15;
    const int rrow = l15 & 7, rsel = l15 >> 3;
    const int bh = blockIdx.y;
    const int b = bh >> 4, h = bh & 15;
    const int q0 = blockIdx.x * 128;

    uint32_t aq[4][4];
    {
        const __nv_bfloat16* r0 = qkv + (size_t)(b * NN + q0 + warp * 16 + gq) * 3072 + h * 64;
        const __nv_bfloat16* r1 = r0 + (size_t)8 * 3072;
        #pragma unroll
        for (int ks = 0; ks < 4; ks++) {
            aq[ks][0] = *(const uint32_t*)(r0 + ks * 16 + 2 * tq);
            aq[ks][1] = *(const uint32_t*)(r1 + ks * 16 + 2 * tq);
            aq[ks][2] = *(const uint32_t*)(r0 + ks * 16 + 2 * tq + 8);
            aq[ks][3] = *(const uint32_t*)(r1 + ks * 16 + 2 * tq + 8);
        }
    }

    float oc[8][4];
    #pragma unroll
    for (int i = 0; i < 8; i++)
        #pragma unroll
        for (int j = 0; j < 4; j++) oc[i][j] = 0.f;
    float m0 = -1e30f, m1 = -1e30f, l0 = 0.f, l1 = 0.f;
    const float qsc = 0.125f * 1.4426950408889634f;

    auto issue_kv = [&](int buf, int kt) {
        #pragma unroll
        for (int it = 0; it < 2; it++) {
            const int e = it * 256 + tid;
            const int row = e >> 3, ch = e & 7;
            const size_t gbase = (size_t)(b * NN + kt * 64 + row) * 3072 + h * 64 + ch * 8;
            cp16(smem_u32(&Kb[buf][row * KVS + ch * 8]), qkv + gbase + 1024);
            cp16(smem_u32(&Vb[buf][row * KVS + ch * 8]), qkv + gbase + 2048);
        }
    };

    issue_kv(0, 0); CP_COMMIT();

    for (int kt = 0; kt < NN / 64; kt++) {
        const int cb = kt & 1;
        issue_kv(cb ^ 1, (kt + 1) & (NN / 64 - 1));
        CP_COMMIT();
        CP_WAIT1();
        __syncthreads();
        const __nv_bfloat16* Ks = Kb[cb];
        const __nv_bfloat16* Vs = Vb[cb];

        float sc[8][4];
        #pragma unroll
        for (int i = 0; i < 8; i++)
            #pragma unroll
            for (int j = 0; j < 4; j++) sc[i][j] = 0.f;
        #pragma unroll
        for (int ks = 0; ks < 4; ks++) {
            #pragma unroll
            for (int nt = 0; nt < 8; nt++) {
                uint32_t bfr[2];
                ldsm_x2(bfr, smem_u32(Ks + (nt * 8 + rrow) * KVS + ks * 16 + rsel * 8));
                mma_bf16(sc[nt], aq[ks], bfr);
            }
        }
        #pragma unroll
        for (int nt = 0; nt < 8; nt++) {
            sc[nt][0] *= qsc; sc[nt][1] *= qsc; sc[nt][2] *= qsc; sc[nt][3] *= qsc;
        }

        float mx0 = -1e30f, mx1 = -1e30f;
        #pragma unroll
        for (int nt = 0; nt < 8; nt++) {
            mx0 = fmaxf(mx0, fmaxf(sc[nt][0], sc[nt][1]));
            mx1 = fmaxf(mx1, fmaxf(sc[nt][2], sc[nt][3]));
        }
        mx0 = fmaxf(mx0, __shfl_xor_sync(0xffffffffu, mx0, 1));
        mx0 = fmaxf(mx0, __shfl_xor_sync(0xffffffffu, mx0, 2));
        mx1 = fmaxf(mx1, __shfl_xor_sync(0xffffffffu, mx1, 1));
        mx1 = fmaxf(mx1, __shfl_xor_sync(0xffffffffu, mx1, 2));
        const float mn0 = fmaxf(m0, mx0), mn1 = fmaxf(m1, mx1);
        const float f0 = ex2(m0 - mn0), f1 = ex2(m1 - mn1);
        m0 = mn0; m1 = mn1;
        l0 *= f0; l1 *= f1;
        #pragma unroll
        for (int dt = 0; dt < 8; dt++) {
            oc[dt][0] *= f0; oc[dt][1] *= f0;
            oc[dt][2] *= f1; oc[dt][3] *= f1;
        }

        #pragma unroll
        for (int j = 0; j < 4; j++) {
            const int t0 = 2 * j, t1 = 2 * j + 1;
            const float p00 = ex2(sc[t0][0] - m0), p01 = ex2(sc[t0][1] - m0);
            const float p02 = ex2(sc[t0][2] - m1), p03 = ex2(sc[t0][3] - m1);
            const float p10 = ex2(sc[t1][0] - m0), p11 = ex2(sc[t1][1] - m0);
            const float p12 = ex2(sc[t1][2] - m1), p13 = ex2(sc[t1][3] - m1);
            l0 += p00 + p01 + p10 + p11;
            l1 += p02 + p03 + p12 + p13;
            uint32_t pa[4] = { pack_bf16(p00, p01), pack_bf16(p02, p03),
                               pack_bf16(p10, p11), pack_bf16(p12, p13) };
            #pragma unroll
            for (int dt = 0; dt < 8; dt++) {
                uint32_t bfr[2];
                ldsm_x2t(bfr, smem_u32(Vs + (16 * j + l15) * KVS + dt * 8));
                mma_bf16(oc[dt], pa, bfr);
            }
        }
        __syncthreads();
    }

    l0 += __shfl_xor_sync(0xffffffffu, l0, 1);
    l0 += __shfl_xor_sync(0xffffffffu, l0, 2);
    l1 += __shfl_xor_sync(0xffffffffu, l1, 1);
    l1 += __shfl_xor_sync(0xffffffffu, l1, 2);
    const float inv0 = 1.f / l0, inv1 = 1.f / l1;
    const int row0 = b * NN + q0 + warp * 16 + gq;
    __nv_bfloat16* o0 = out + (size_t)row0 * EE + h * 64;
    __nv_bfloat16* o1 = o0 + (size_t)8 * EE;
    #pragma unroll
    for (int dt = 0; dt < 8; dt++) {
        *(uint32_t*)(o0 + dt * 8 + 2 * tq) = pack_bf16(oc[dt][0] * inv0, oc[dt][1] * inv0);
        *(uint32_t*)(o1 + dt * 8 + 2 * tq) = pack_bf16(oc[dt][2] * inv1, oc[dt][3] * inv1);
    }
}

// ---------------- host launch ---------------------------------------------------
extern "C" void kernel_launch(void* const* d_in, const int* in_sizes, int n_in,
                              void* d_out, int out_size) {
    const float* x      = (const float*)d_in[0];
    const float* w_qkv  = (const float*)d_in[1];
    const float* b_qkv  = (const float*)d_in[2];
    const float* w_proj = (const float*)d_in[3];
    const float* b_proj = (const float*)d_in[4];
    const float* g1     = (const float*)d_in[5];
    const float* beta1  = (const float*)d_in[6];
    const float* g2     = (const float*)d_in[7];
    const float* beta2  = (const float*)d_in[8];
    const float* w_fc1  = (const float*)d_in[9];
    const float* b_fc1  = (const float*)d_in[10];
    const float* w_fc2  = (const float*)d_in[11];
    const float* b_fc2  = (const float*)d_in[12];
    float* out = (float*)d_out;

    __nv_bfloat16 *h, *qkv, *attn, *mlp, *wqkvT, *wprojT, *wfc1T, *wfc2T;
    float* x1;
    cudaGetSymbolAddress((void**)&h,      g_h);
    cudaGetSymbolAddress((void**)&qkv,    g_qkv);
    cudaGetSymbolAddress((void**)&attn,   g_attn);
    cudaGetSymbolAddress((void**)&x1,     g_x1);
    cudaGetSymbolAddress((void**)&mlp,    g_mlp);
    cudaGetSymbolAddress((void**)&wqkvT,  g_wqkvT);
    cudaGetSymbolAddress((void**)&wprojT, g_wprojT);
    cudaGetSymbolAddress((void**)&wfc1T,  g_wfc1T);
    cudaGetSymbolAddress((void**)&wfc2T,  g_wfc2T);

    cudaFuncSetAttribute(gemm_mma<0>, cudaFuncAttributeMaxDynamicSharedMemorySize, GEMM_SMEM_BYTES);
    cudaFuncSetAttribute(gemm_mma<1>, cudaFuncAttributeMaxDynamicSharedMemorySize, GEMM_SMEM_BYTES);
    cudaFuncSetAttribute(gemm_mma<2>, cudaFuncAttributeMaxDynamicSharedMemorySize, GEMM_SMEM_BYTES);

    // single fused transpose launch for all 4 weights
    transpose_all<<<T_FC2, dim3(32, 8)>>>(w_qkv, w_proj, w_fc1, w_fc2,
                                          wqkvT, wprojT, wfc1T, wfc2T);

    // 1. h = LN(x) -> bf16
    ln_kernel<<<MR, 256>>>(x, g1, beta1, h);
    // 2. qkv = h @ w_qkv + b_qkv -> bf16
    gemm_mma<0><<<dim3(3 * EE / 256, MR / 128), 256, GEMM_SMEM_BYTES>>>(
        h, wqkvT, b_qkv, nullptr, qkv, MR, 3 * EE, EE);
    // 3. attention -> bf16
    attn_mma<<<dim3(NN / 128, BB * HH), 256>>>(qkv, attn);
    // 4. x1 = attn @ w_proj + b_proj + x -> fp32
    gemm_mma<2><<<dim3(EE / 256, MR / 128), 256, GEMM_SMEM_BYTES>>>(
        attn, wprojT, b_proj, x, x1, MR, EE, EE);
    // 5. h = LN(x1) -> bf16
    ln_kernel<<<MR, 256>>>(x1, g2, beta2, h);
    // 6. mlp = gelu(h @ w_fc1 + b_fc1) -> bf16
    gemm_mma<1><<<dim3(MLPD / 256, MR / 128), 256, GEMM_SMEM_BYTES>>>(
        h, wfc1T, b_fc1, nullptr, mlp, MR, MLPD, EE);
    // 7. out = mlp @ w_fc2 + b_fc2 + x1 -> fp32
    gemm_mma<2><<<dim3(EE / 256, MR / 128), 256, GEMM_SMEM_BYTES>>>(
        mlp, wfc2T, b_fc2, x1, out, MR, EE, MLPD);
}

// round 8
// speedup vs baseline: 7.2088x; 1.0428x over previous
#include <cuda_runtime.h>
#include <cuda_bf16.h>
#include <math.h>
#include <stdint.h>

// Problem constants
#define BB   2
#define NN   2048
#define EE   1024
#define HH   16
#define MLPD 4096
#define MR   (BB * NN)   // 4096 token rows

// ---------------- scratch (static device globals; no allocation) ----------------
__device__ __nv_bfloat16 g_h[MR * EE];               // LN output (bf16)
__device__ __nv_bfloat16 g_qkv[MR * 3 * EE];         // QKV (bf16)
__device__ __nv_bfloat16 g_attn[MR * EE];            // attention out (bf16)
__device__ float         g_x1[MR * EE];              // residual 1 (fp32)
__device__ __nv_bfloat16 g_mlp[(size_t)MR * MLPD];   // GELU(fc1) (bf16)
__device__ __nv_bfloat16 g_wqkvT[3 * EE * EE];       // transposed weights [N,K] bf16
__device__ __nv_bfloat16 g_wprojT[EE * EE];
__device__ __nv_bfloat16 g_wfc1T[(size_t)MLPD * EE];
__device__ __nv_bfloat16 g_wfc2T[(size_t)EE * MLPD];

// ======================= helpers =================================
__device__ __forceinline__ uint32_t smem_u32(const void* p) {
    uint32_t a;
    asm("{ .reg .u64 t; cvta.to.shared.u64 t, %1; cvt.u32.u64 %0, t; }" : "=r"(a) : "l"(p));
    return a;
}
__device__ __forceinline__ float ex2(float x) {
    float r;
    asm("ex2.approx.ftz.f32 %0, %1;" : "=f"(r) : "f"(x));
    return r;
}
__device__ __forceinline__ uint32_t pack_bf16(float lo, float hi) {
    uint32_t r;
    asm("cvt.rn.bf16x2.f32 %0, %1, %2;" : "=r"(r) : "f"(hi), "f"(lo));
    return r;
}
__device__ __forceinline__ uint32_t scale_bf16x2(uint32_t v, float s) {
    const __nv_bfloat162 b = *reinterpret_cast<const __nv_bfloat162*>(&v);
    return pack_bf16(__bfloat162float(b.x) * s, __bfloat162float(b.y) * s);
}
__device__ __forceinline__ void cp16(uint32_t dst, const void* src) {
    asm volatile("cp.async.cg.shared.global [%0], [%1], 16;" :: "r"(dst), "l"(src));
}
#define CP_COMMIT() asm volatile("cp.async.commit_group;" ::: "memory")
#define CP_WAIT1()  asm volatile("cp.async.wait_group 1;" ::: "memory")

__device__ __forceinline__ void mma_bf16(float* c, const uint32_t* a, const uint32_t* b) {
    asm volatile(
        "mma.sync.aligned.m16n8k16.row.col.f32.bf16.bf16.f32 "
        "{%0,%1,%2,%3}, {%4,%5,%6,%7}, {%8,%9}, {%0,%1,%2,%3};"
        : "+f"(c[0]), "+f"(c[1]), "+f"(c[2]), "+f"(c[3])
        : "r"(a[0]), "r"(a[1]), "r"(a[2]), "r"(a[3]), "r"(b[0]), "r"(b[1]));
}
__device__ __forceinline__ void ldsm_x4(uint32_t* r, uint32_t addr) {
    asm volatile("ldmatrix.sync.aligned.m8n8.x4.shared.b16 {%0,%1,%2,%3}, [%4];"
                 : "=r"(r[0]), "=r"(r[1]), "=r"(r[2]), "=r"(r[3]) : "r"(addr));
}
__device__ __forceinline__ void ldsm_x4t(uint32_t* r, uint32_t addr) {
    asm volatile("ldmatrix.sync.aligned.m8n8.x4.trans.shared.b16 {%0,%1,%2,%3}, [%4];"
                 : "=r"(r[0]), "=r"(r[1]), "=r"(r[2]), "=r"(r[3]) : "r"(addr));
}

// ---------------- fused transpose of all 4 weights: one launch -------------------
#define T_QKV  3072
#define T_PROJ (T_QKV + 1024)
#define T_FC1  (T_PROJ + 4096)
#define T_FC2  (T_FC1 + 4096)

__global__ void transpose_all(const float* __restrict__ w0, const float* __restrict__ w1,
                              const float* __restrict__ w2, const float* __restrict__ w3,
                              __nv_bfloat16* __restrict__ o0, __nv_bfloat16* __restrict__ o1,
                              __nv_bfloat16* __restrict__ o2, __nv_bfloat16* __restrict__ o3) {
    __shared__ float t[32][33];
    int tt = blockIdx.x;
    const float* in;
    __nv_bfloat16* out;
    int R, C;
    if (tt < T_QKV)       { in = w0; out = o0; R = EE;   C = 3 * EE; }
    else if (tt < T_PROJ) { in = w1; out = o1; R = EE;   C = EE;   tt -= T_QKV;  }
    else if (tt < T_FC1)  { in = w2; out = o2; R = EE;   C = MLPD; tt -= T_PROJ; }
    else                  { in = w3; out = o3; R = MLPD; C = EE;   tt -= T_FC1;  }
    const int ctiles = C >> 5;
    const int bx = tt % ctiles, by = tt / ctiles;

    const int c = bx * 32 + threadIdx.x;
    const int r0 = by * 32;
    #pragma unroll
    for (int i = threadIdx.y; i < 32; i += 8)
        t[i][threadIdx.x] = in[(size_t)(r0 + i) * C + c];
    __syncthreads();
    const int rc = by * 32 + threadIdx.x;
    const int c0 = bx * 32;
    #pragma unroll
    for (int i = threadIdx.y; i < 32; i += 8)
        out[(size_t)(c0 + i) * R + rc] = __float2bfloat16_rn(t[threadIdx.x][i]);
}

// ---------------- LayerNorm fp32 -> bf16 -----------------------------------------
__global__ void ln_kernel(const float* __restrict__ x, const float* __restrict__ g,
                          const float* __restrict__ beta,
                          __nv_bfloat16* __restrict__ out) {
    __shared__ float sh[8];
    const int row = blockIdx.x;
    const int tid = threadIdx.x;
    const float4 v = ((const float4*)(x + (size_t)row * EE))[tid];

    float s = v.x + v.y + v.z + v.w;
    #pragma unroll
    for (int o = 16; o; o >>= 1) s += __shfl_down_sync(0xffffffffu, s, o);
    if ((tid & 31) == 0) sh[tid >> 5] = s;
    __syncthreads();
    if (tid < 32) {
        float t = (tid < 8) ? sh[tid] : 0.f;
        #pragma unroll
        for (int o = 4; o; o >>= 1) t += __shfl_down_sync(0xffffffffu, t, o);
        if (tid == 0) sh[0] = t;
    }
    __syncthreads();
    const float mu = sh[0] * (1.0f / EE);
    __syncthreads();

    float dx = v.x - mu, dy = v.y - mu, dz = v.z - mu, dw = v.w - mu;
    float q = dx * dx + dy * dy + dz * dz + dw * dw;
    #pragma unroll
    for (int o = 16; o; o >>= 1) q += __shfl_down_sync(0xffffffffu, q, o);
    if ((tid & 31) == 0) sh[tid >> 5] = q;
    __syncthreads();
    if (tid < 32) {
        float t = (tid < 8) ? sh[tid] : 0.f;
        #pragma unroll
        for (int o = 4; o; o >>= 1) t += __shfl_down_sync(0xffffffffu, t, o);
        if (tid == 0) sh[0] = t;
    }
    __syncthreads();
    const float rstd = rsqrtf(sh[0] * (1.0f / EE) + 1e-5f);

    const float4 gv = ((const float4*)g)[tid];
    const float4 bv = ((const float4*)beta)[tid];
    uint2 o;
    o.x = pack_bf16(dx * rstd * gv.x + bv.x, dy * rstd * gv.y + bv.y);
    o.y = pack_bf16(dz * rstd * gv.z + bv.z, dw * rstd * gv.w + bv.w);
    ((uint2*)(out + (size_t)row * EE))[tid] = o;
}

// ---------------- bf16 mma.sync GEMM: CTA 128x256, 3-stage, x4 ldmatrix ----------
#define ASTR 72
#define STG  ((128 + 256) * ASTR)
#define GEMM_SMEM_BYTES (3 * STG * 2)

__device__ __forceinline__ void issue_tile(const __nv_bfloat16* __restrict__ A,
                                           const __nv_bfloat16* __restrict__ BT,
                                           __nv_bfloat16* stage, int bm, int bn,
                                           int kc, int K, int tid) {
    __nv_bfloat16* sA = stage;
    __nv_bfloat16* sB = stage + 128 * ASTR;
    #pragma unroll
    for (int p = 0; p < 4; p++) {
        const int e = p * 256 + tid;
        const int row = e >> 3, ch = e & 7;
        cp16(smem_u32(sA + row * ASTR + ch * 8),
             A + (size_t)(bm + row) * K + kc * 64 + ch * 8);
    }
    #pragma unroll
    for (int p = 0; p < 8; p++) {
        const int e = p * 256 + tid;
        const int row = e >> 3, ch = e & 7;
        cp16(smem_u32(sB + row * ASTR + ch * 8),
             BT + (size_t)(bn + row) * K + kc * 64 + ch * 8);
    }
}

template <int EPI>
__global__ __launch_bounds__(256, 1)
void gemm_mma(const __nv_bfloat16* __restrict__ A, const __nv_bfloat16* __restrict__ BT,
              const float* __restrict__ bias, const float* __restrict__ res,
              void* __restrict__ Cout, int M, int N, int K) {
    extern __shared__ __align__(16) __nv_bfloat16 smem[];
    const int tid  = threadIdx.x;
    const int lane = tid & 31, warp = tid >> 5;
    const int wm = warp >> 2, wn = warp & 3;
    const int gq = lane >> 2, tq = lane & 3;
    const int l15 = lane & 15;
    const int arow = l15, asel = lane >> 4;              // A ldsm.x4 addressing
    const int g  = lane >> 3, r8 = lane & 7;             // B ldsm.x4 pairing
    const int brow_off = (g >> 1) * 8 + r8;              // row within nt-pair
    const int bcol_off = (g & 1) * 8;                    // k sub-chunk
    const int bm = blockIdx.y << 7;
    const int bn = blockIdx.x << 8;
    const int NC = K >> 6;

    float c[4][8][4];
    #pragma unroll
    for (int i = 0; i < 4; i++)
        #pragma unroll
        for (int j = 0; j < 8; j++)
            #pragma unroll
            for (int k = 0; k < 4; k++) c[i][j][k] = 0.f;

    issue_tile(A, BT, smem,       bm, bn, 0, K, tid); CP_COMMIT();
    issue_tile(A, BT, smem + STG, bm, bn, 1, K, tid); CP_COMMIT();

    int st = 0;
    for (int kc = 0; kc < NC; kc++) {
        CP_WAIT1();
        __syncthreads();
        if (kc + 2 < NC) {
            int nst = st + 2; if (nst >= 3) nst -= 3;
            issue_tile(A, BT, smem + nst * STG, bm, bn, kc + 2, K, tid);
        }
        CP_COMMIT();
        const __nv_bfloat16* sa = smem + st * STG + (size_t)(wm * 64) * ASTR;
        const __nv_bfloat16* sb = smem + st * STG + (size_t)128 * ASTR + (size_t)(wn * 64) * ASTR;
        #pragma unroll
        for (int ks = 0; ks < 4; ks++) {
            uint32_t af[4][4], bf[4][4];
            #pragma unroll
            for (int mt = 0; mt < 4; mt++)
                ldsm_x4(af[mt], smem_u32(sa + (mt * 16 + arow) * ASTR + ks * 16 + asel * 8));
            #pragma unroll
            for (int np = 0; np < 4; np++)
                ldsm_x4(bf[np], smem_u32(sb + (np * 16 + brow_off) * ASTR + ks * 16 + bcol_off));
            #pragma unroll
            for (int mt = 0; mt < 4; mt++)
                #pragma unroll
                for (int np = 0; np < 4; np++) {
                    mma_bf16(c[mt][2 * np + 0], af[mt], bf[np] + 0);
                    mma_bf16(c[mt][2 * np + 1], af[mt], bf[np] + 2);
                }
        }
        if (++st >= 3) st = 0;
    }

    // ---- epilogue ----
    #pragma unroll
    for (int nt = 0; nt < 8; nt++) {
        const int col = bn + wn * 64 + nt * 8 + 2 * tq;
        const float bx = bias[col], by = bias[col + 1];
        #pragma unroll
        for (int mt = 0; mt < 4; mt++) {
            const int row0 = bm + wm * 64 + mt * 16 + gq;
            #pragma unroll
            for (int half = 0; half < 2; half++) {
                const int row = row0 + half * 8;
                float vx = c[mt][nt][half * 2 + 0] + bx;
                float vy = c[mt][nt][half * 2 + 1] + by;
                if (EPI == 1) {
                    vx = 0.5f * vx * (1.0f + erff(vx * 0.70710678118654752f));
                    vy = 0.5f * vy * (1.0f + erff(vy * 0.70710678118654752f));
                }
                if (EPI == 2) {
                    const float2 rv = *(const float2*)(res + (size_t)row * N + col);
                    float2 o; o.x = vx + rv.x; o.y = vy + rv.y;
                    *(float2*)((float*)Cout + (size_t)row * N + col) = o;
                } else {
                    *(uint32_t*)((__nv_bfloat16*)Cout + (size_t)row * N + col) =
                        pack_bf16(vx, vy);
                }
            }
        }
    }
}

// ---------------- Flash attention, bf16 mma.sync, x4 ldmatrix, pre-scaled Q ------
#define KVS 72

__global__ __launch_bounds__(256, 2)
void attn_mma(const __nv_bfloat16* __restrict__ qkv, __nv_bfloat16* __restrict__ out) {
    __shared__ __nv_bfloat16 Kb[2][64 * KVS];
    __shared__ __nv_bfloat16 Vb[2][64 * KVS];
    const int tid  = threadIdx.x;
    const int lane = tid & 31, warp = tid >> 5;
    const int gq = lane >> 2, tq = lane & 3;
    const int g  = lane >> 3, r8 = lane & 7;
    const int krow_off = (g >> 1) * 8 + r8;      // K ldsm.x4 pairing (nt pairs)
    const int kcol_off = (g & 1) * 8;
    const int vrow_off = (g & 1) * 8 + r8;       // V ldsm.x4.trans pairing (dt pairs)
    const int vcol_off = (g >> 1) * 8;
    const int bh = blockIdx.y;
    const int b = bh >> 4, h = bh & 15;
    const int q0 = blockIdx.x * 128;

    // ---- Q fragments, pre-scaled by D^-0.5 * log2(e), packed bf16x2 ----
    const float qsc = 0.125f * 1.4426950408889634f;
    uint32_t aq[4][4];
    {
        const __nv_bfloat16* r0 = qkv + (size_t)(b * NN + q0 + warp * 16 + gq) * 3072 + h * 64;
        const __nv_bfloat16* r1 = r0 + (size_t)8 * 3072;
        #pragma unroll
        for (int ks = 0; ks < 4; ks++) {
            aq[ks][0] = scale_bf16x2(*(const uint32_t*)(r0 + ks * 16 + 2 * tq), qsc);
            aq[ks][1] = scale_bf16x2(*(const uint32_t*)(r1 + ks * 16 + 2 * tq), qsc);
            aq[ks][2] = scale_bf16x2(*(const uint32_t*)(r0 + ks * 16 + 2 * tq + 8), qsc);
            aq[ks][3] = scale_bf16x2(*(const uint32_t*)(r1 + ks * 16 + 2 * tq + 8), qsc);
        }
    }

    float oc[8][4];
    #pragma unroll
    for (int i = 0; i < 8; i++)
        #pragma unroll
        for (int j = 0; j < 4; j++) oc[i][j] = 0.f;
    float m0 = -1e30f, m1 = -1e30f, l0 = 0.f, l1 = 0.f;

    auto issue_kv = [&](int buf, int kt) {
        #pragma unroll
        for (int it = 0; it < 2; it++) {
            const int e = it * 256 + tid;
            const int row = e >> 3, ch = e & 7;
            const size_t gbase = (size_t)(b * NN + kt * 64 + row) * 3072 + h * 64 + ch * 8;
            cp16(smem_u32(&Kb[buf][row * KVS + ch * 8]), qkv + gbase + 1024);
            cp16(smem_u32(&Vb[buf][row * KVS + ch * 8]), qkv + gbase + 2048);
        }
    };

    issue_kv(0, 0); CP_COMMIT();

    for (int kt = 0; kt < NN / 64; kt++) {
        const int cb = kt & 1;
        issue_kv(cb ^ 1, (kt + 1) & (NN / 64 - 1));
        CP_COMMIT();
        CP_WAIT1();
        __syncthreads();
        const __nv_bfloat16* Ks = Kb[cb];
        const __nv_bfloat16* Vs = Vb[cb];

        // ---- S = Q_scaled K^T (log2 domain) ----
        float sc[8][4];
        #pragma unroll
        for (int i = 0; i < 8; i++)
            #pragma unroll
            for (int j = 0; j < 4; j++) sc[i][j] = 0.f;
        #pragma unroll
        for (int ks = 0; ks < 4; ks++) {
            #pragma unroll
            for (int np = 0; np < 4; np++) {
                uint32_t b4[4];
                ldsm_x4(b4, smem_u32(Ks + (np * 16 + krow_off) * KVS + ks * 16 + kcol_off));
                mma_bf16(sc[2 * np + 0], aq[ks], b4 + 0);
                mma_bf16(sc[2 * np + 1], aq[ks], b4 + 2);
            }
        }

        // ---- online softmax (exp2 domain) ----
        float mx0 = -1e30f, mx1 = -1e30f;
        #pragma unroll
        for (int nt = 0; nt < 8; nt++) {
            mx0 = fmaxf(mx0, fmaxf(sc[nt][0], sc[nt][1]));
            mx1 = fmaxf(mx1, fmaxf(sc[nt][2], sc[nt][3]));
        }
        mx0 = fmaxf(mx0, __shfl_xor_sync(0xffffffffu, mx0, 1));
        mx0 = fmaxf(mx0, __shfl_xor_sync(0xffffffffu, mx0, 2));
        mx1 = fmaxf(mx1, __shfl_xor_sync(0xffffffffu, mx1, 1));
        mx1 = fmaxf(mx1, __shfl_xor_sync(0xffffffffu, mx1, 2));
        const float mn0 = fmaxf(m0, mx0), mn1 = fmaxf(m1, mx1);
        const float f0 = ex2(m0 - mn0), f1 = ex2(m1 - mn1);
        m0 = mn0; m1 = mn1;
        l0 *= f0; l1 *= f1;
        #pragma unroll
        for (int dt = 0; dt < 8; dt++) {
            oc[dt][0] *= f0; oc[dt][1] *= f0;
            oc[dt][2] *= f1; oc[dt][3] *= f1;
        }

        // ---- P = exp2(S - m); PV accumulate ----
        #pragma unroll
        for (int j = 0; j < 4; j++) {
            const int t0 = 2 * j, t1 = 2 * j + 1;
            const float p00 = ex2(sc[t0][0] - m0), p01 = ex2(sc[t0][1] - m0);
            const float p02 = ex2(sc[t0][2] - m1), p03 = ex2(sc[t0][3] - m1);
            const float p10 = ex2(sc[t1][0] - m0), p11 = ex2(sc[t1][1] - m0);
            const float p12 = ex2(sc[t1][2] - m1), p13 = ex2(sc[t1][3] - m1);
            l0 += p00 + p01 + p10 + p11;
            l1 += p02 + p03 + p12 + p13;
            uint32_t pa[4] = { pack_bf16(p00, p01), pack_bf16(p02, p03),
                               pack_bf16(p10, p11), pack_bf16(p12, p13) };
            #pragma unroll
            for (int dp = 0; dp < 4; dp++) {
                uint32_t b4[4];
                ldsm_x4t(b4, smem_u32(Vs + (16 * j + vrow_off) * KVS + dp * 16 + vcol_off));
                mma_bf16(oc[2 * dp + 0], pa, b4 + 0);
                mma_bf16(oc[2 * dp + 1], pa, b4 + 2);
            }
        }
        __syncthreads();
    }

    // ---- finalize ----
    l0 += __shfl_xor_sync(0xffffffffu, l0, 1);
    l0 += __shfl_xor_sync(0xffffffffu, l0, 2);
    l1 += __shfl_xor_sync(0xffffffffu, l1, 1);
    l1 += __shfl_xor_sync(0xffffffffu, l1, 2);
    const float inv0 = 1.f / l0, inv1 = 1.f / l1;
    const int row0 = b * NN + q0 + warp * 16 + gq;
    __nv_bfloat16* o0 = out + (size_t)row0 * EE + h * 64;
    __nv_bfloat16* o1 = o0 + (size_t)8 * EE;
    #pragma unroll
    for (int dt = 0; dt < 8; dt++) {
        *(uint32_t*)(o0 + dt * 8 + 2 * tq) = pack_bf16(oc[dt][0] * inv0, oc[dt][1] * inv0);
        *(uint32_t*)(o1 + dt * 8 + 2 * tq) = pack_bf16(oc[dt][2] * inv1, oc[dt][3] * inv1);
    }
}

// ---------------- host launch ---------------------------------------------------
extern "C" void kernel_launch(void* const* d_in, const int* in_sizes, int n_in,
                              void* d_out, int out_size) {
    const float* x      = (const float*)d_in[0];
    const float* w_qkv  = (const float*)d_in[1];
    const float* b_qkv  = (const float*)d_in[2];
    const float* w_proj = (const float*)d_in[3];
    const float* b_proj = (const float*)d_in[4];
    const float* g1     = (const float*)d_in[5];
    const float* beta1  = (const float*)d_in[6];
    const float* g2     = (const float*)d_in[7];
    const float* beta2  = (const float*)d_in[8];
    const float* w_fc1  = (const float*)d_in[9];
    const float* b_fc1  = (const float*)d_in[10];
    const float* w_fc2  = (const float*)d_in[11];
    const float* b_fc2  = (const float*)d_in[12];
    float* out = (float*)d_out;

    __nv_bfloat16 *h, *qkv, *attn, *mlp, *wqkvT, *wprojT, *wfc1T, *wfc2T;
    float* x1;
    cudaGetSymbolAddress((void**)&h,      g_h);
    cudaGetSymbolAddress((void**)&qkv,    g_qkv);
    cudaGetSymbolAddress((void**)&attn,   g_attn);
    cudaGetSymbolAddress((void**)&x1,     g_x1);
    cudaGetSymbolAddress((void**)&mlp,    g_mlp);
    cudaGetSymbolAddress((void**)&wqkvT,  g_wqkvT);
    cudaGetSymbolAddress((void**)&wprojT, g_wprojT);
    cudaGetSymbolAddress((void**)&wfc1T,  g_wfc1T);
    cudaGetSymbolAddress((void**)&wfc2T,  g_wfc2T);

    cudaFuncSetAttribute(gemm_mma<0>, cudaFuncAttributeMaxDynamicSharedMemorySize, GEMM_SMEM_BYTES);
    cudaFuncSetAttribute(gemm_mma<1>, cudaFuncAttributeMaxDynamicSharedMemorySize, GEMM_SMEM_BYTES);
    cudaFuncSetAttribute(gemm_mma<2>, cudaFuncAttributeMaxDynamicSharedMemorySize, GEMM_SMEM_BYTES);

    transpose_all<<<T_FC2, dim3(32, 8)>>>(w_qkv, w_proj, w_fc1, w_fc2,
                                          wqkvT, wprojT, wfc1T, wfc2T);

    // 1. h = LN(x) -> bf16
    ln_kernel<<<MR, 256>>>(x, g1, beta1, h);
    // 2. qkv = h @ w_qkv + b_qkv -> bf16
    gemm_mma<0><<<dim3(3 * EE / 256, MR / 128), 256, GEMM_SMEM_BYTES>>>(
        h, wqkvT, b_qkv, nullptr, qkv, MR, 3 * EE, EE);
    // 3. attention -> bf16
    attn_mma<<<dim3(NN / 128, BB * HH), 256>>>(qkv, attn);
    // 4. x1 = attn @ w_proj + b_proj + x -> fp32
    gemm_mma<2><<<dim3(EE / 256, MR / 128), 256, GEMM_SMEM_BYTES>>>(
        attn, wprojT, b_proj, x, x1, MR, EE, EE);
    // 5. h = LN(x1) -> bf16
    ln_kernel<<<MR, 256>>>(x1, g2, beta2, h);
    // 6. mlp = gelu(h @ w_fc1 + b_fc1) -> bf16
    gemm_mma<1><<<dim3(MLPD / 256, MR / 128), 256, GEMM_SMEM_BYTES>>>(
        h, wfc1T, b_fc1, nullptr, mlp, MR, MLPD, EE);
    // 7. out = mlp @ w_fc2 + b_fc2 + x1 -> fp32
    gemm_mma<2><<<dim3(EE / 256, MR / 128), 256, GEMM_SMEM_BYTES>>>(
        mlp, wfc2T, b_fc2, x1, out, MR, EE, MLPD);
}

// round 9
// speedup vs baseline: 7.4212x; 1.0295x over previous
#include <cuda_runtime.h>
#include <cuda_bf16.h>
#include <math.h>
#include <stdint.h>

// Problem constants
#define BB   2
#define NN   2048
#define EE   1024
#define HH   16
#define MLPD 4096
#define MR   (BB * NN)   // 4096 token rows

// ---------------- scratch (static device globals; no allocation) ----------------
__device__ __nv_bfloat16 g_h[MR * EE];               // LN output (bf16)
__device__ __nv_bfloat16 g_qkv[MR * 3 * EE];         // QKV (bf16)
__device__ __nv_bfloat16 g_attn[MR * EE];            // attention out (bf16)
__device__ float         g_x1[MR * EE];              // residual 1 (fp32)
__device__ __nv_bfloat16 g_mlp[(size_t)MR * MLPD];   // GELU(fc1) (bf16)
__device__ __nv_bfloat16 g_wqkvT[3 * EE * EE];       // transposed weights [N,K] bf16
__device__ __nv_bfloat16 g_wprojT[EE * EE];
__device__ __nv_bfloat16 g_wfc1T[(size_t)MLPD * EE];
__device__ __nv_bfloat16 g_wfc2T[(size_t)EE * MLPD];

// ======================= helpers =================================
__device__ __forceinline__ uint32_t smem_u32(const void* p) {
    uint32_t a;
    asm("{ .reg .u64 t; cvta.to.shared.u64 t, %1; cvt.u32.u64 %0, t; }" : "=r"(a) : "l"(p));
    return a;
}
__device__ __forceinline__ float ex2(float x) {
    float r;
    asm("ex2.approx.ftz.f32 %0, %1;" : "=f"(r) : "f"(x));
    return r;
}
__device__ __forceinline__ uint32_t pack_bf16(float lo, float hi) {
    uint32_t r;
    asm("cvt.rn.bf16x2.f32 %0, %1, %2;" : "=r"(r) : "f"(hi), "f"(lo));
    return r;
}
__device__ __forceinline__ uint32_t scale_bf16x2(uint32_t v, float s) {
    const __nv_bfloat162 b = *reinterpret_cast<const __nv_bfloat162*>(&v);
    return pack_bf16(__bfloat162float(b.x) * s, __bfloat162float(b.y) * s);
}
__device__ __forceinline__ void cp16(uint32_t dst, const void* src) {
    asm volatile("cp.async.cg.shared.global [%0], [%1], 16;" :: "r"(dst), "l"(src));
}
#define CP_COMMIT() asm volatile("cp.async.commit_group;" ::: "memory")
#define CP_WAIT1()  asm volatile("cp.async.wait_group 1;" ::: "memory")

__device__ __forceinline__ void mma_bf16(float* c, const uint32_t* a, const uint32_t* b) {
    asm volatile(
        "mma.sync.aligned.m16n8k16.row.col.f32.bf16.bf16.f32 "
        "{%0,%1,%2,%3}, {%4,%5,%6,%7}, {%8,%9}, {%0,%1,%2,%3};"
        : "+f"(c[0]), "+f"(c[1]), "+f"(c[2]), "+f"(c[3])
        : "r"(a[0]), "r"(a[1]), "r"(a[2]), "r"(a[3]), "r"(b[0]), "r"(b[1]));
}
__device__ __forceinline__ void ldsm_x4(uint32_t* r, uint32_t addr) {
    asm volatile("ldmatrix.sync.aligned.m8n8.x4.shared.b16 {%0,%1,%2,%3}, [%4];"
                 : "=r"(r[0]), "=r"(r[1]), "=r"(r[2]), "=r"(r[3]) : "r"(addr));
}
__device__ __forceinline__ void ldsm_x4t(uint32_t* r, uint32_t addr) {
    asm volatile("ldmatrix.sync.aligned.m8n8.x4.trans.shared.b16 {%0,%1,%2,%3}, [%4];"
                 : "=r"(r[0]), "=r"(r[1]), "=r"(r[2]), "=r"(r[3]) : "r"(addr));
}

// ---------------- fused transpose of all 4 weights: one launch -------------------
#define T_QKV  3072
#define T_PROJ (T_QKV + 1024)
#define T_FC1  (T_PROJ + 4096)
#define T_FC2  (T_FC1 + 4096)

__global__ void transpose_all(const float* __restrict__ w0, const float* __restrict__ w1,
                              const float* __restrict__ w2, const float* __restrict__ w3,
                              __nv_bfloat16* __restrict__ o0, __nv_bfloat16* __restrict__ o1,
                              __nv_bfloat16* __restrict__ o2, __nv_bfloat16* __restrict__ o3) {
    __shared__ float t[32][33];
    int tt = blockIdx.x;
    const float* in;
    __nv_bfloat16* out;
    int R, C;
    if (tt < T_QKV)       { in = w0; out = o0; R = EE;   C = 3 * EE; }
    else if (tt < T_PROJ) { in = w1; out = o1; R = EE;   C = EE;   tt -= T_QKV;  }
    else if (tt < T_FC1)  { in = w2; out = o2; R = EE;   C = MLPD; tt -= T_PROJ; }
    else                  { in = w3; out = o3; R = MLPD; C = EE;   tt -= T_FC1;  }
    const int ctiles = C >> 5;
    const int bx = tt % ctiles, by = tt / ctiles;

    const int c = bx * 32 + threadIdx.x;
    const int r0 = by * 32;
    #pragma unroll
    for (int i = threadIdx.y; i < 32; i += 8)
        t[i][threadIdx.x] = in[(size_t)(r0 + i) * C + c];
    __syncthreads();
    const int rc = by * 32 + threadIdx.x;
    const int c0 = bx * 32;
    #pragma unroll
    for (int i = threadIdx.y; i < 32; i += 8)
        out[(size_t)(c0 + i) * R + rc] = __float2bfloat16_rn(t[threadIdx.x][i]);
}

// ---------------- LayerNorm fp32 -> bf16 -----------------------------------------
__global__ void ln_kernel(const float* __restrict__ x, const float* __restrict__ g,
                          const float* __restrict__ beta,
                          __nv_bfloat16* __restrict__ out) {
    __shared__ float sh[8];
    const int row = blockIdx.x;
    const int tid = threadIdx.x;
    const float4 v = ((const float4*)(x + (size_t)row * EE))[tid];

    float s = v.x + v.y + v.z + v.w;
    #pragma unroll
    for (int o = 16; o; o >>= 1) s += __shfl_down_sync(0xffffffffu, s, o);
    if ((tid & 31) == 0) sh[tid >> 5] = s;
    __syncthreads();
    if (tid < 32) {
        float t = (tid < 8) ? sh[tid] : 0.f;
        #pragma unroll
        for (int o = 4; o; o >>= 1) t += __shfl_down_sync(0xffffffffu, t, o);
        if (tid == 0) sh[0] = t;
    }
    __syncthreads();
    const float mu = sh[0] * (1.0f / EE);
    __syncthreads();

    float dx = v.x - mu, dy = v.y - mu, dz = v.z - mu, dw = v.w - mu;
    float q = dx * dx + dy * dy + dz * dz + dw * dw;
    #pragma unroll
    for (int o = 16; o; o >>= 1) q += __shfl_down_sync(0xffffffffu, q, o);
    if ((tid & 31) == 0) sh[tid >> 5] = q;
    __syncthreads();
    if (tid < 32) {
        float t = (tid < 8) ? sh[tid] : 0.f;
        #pragma unroll
        for (int o = 4; o; o >>= 1) t += __shfl_down_sync(0xffffffffu, t, o);
        if (tid == 0) sh[0] = t;
    }
    __syncthreads();
    const float rstd = rsqrtf(sh[0] * (1.0f / EE) + 1e-5f);

    const float4 gv = ((const float4*)g)[tid];
    const float4 bv = ((const float4*)beta)[tid];
    uint2 o;
    o.x = pack_bf16(dx * rstd * gv.x + bv.x, dy * rstd * gv.y + bv.y);
    o.y = pack_bf16(dz * rstd * gv.z + bv.z, dw * rstd * gv.w + bv.w);
    ((uint2*)(out + (size_t)row * EE))[tid] = o;
}

// ---------------- bf16 mma.sync GEMM: CTA 128x256, 3-stage, x4 ldmatrix ----------
#define ASTR 72
#define STG  ((128 + 256) * ASTR)
#define GEMM_SMEM_BYTES (3 * STG * 2)

__device__ __forceinline__ void issue_tile(const __nv_bfloat16* __restrict__ A,
                                           const __nv_bfloat16* __restrict__ BT,
                                           __nv_bfloat16* stage, int bm, int bn,
                                           int kc, int K, int tid) {
    __nv_bfloat16* sA = stage;
    __nv_bfloat16* sB = stage + 128 * ASTR;
    #pragma unroll
    for (int p = 0; p < 4; p++) {
        const int e = p * 256 + tid;
        const int row = e >> 3, ch = e & 7;
        cp16(smem_u32(sA + row * ASTR + ch * 8),
             A + (size_t)(bm + row) * K + kc * 64 + ch * 8);
    }
    #pragma unroll
    for (int p = 0; p < 8; p++) {
        const int e = p * 256 + tid;
        const int row = e >> 3, ch = e & 7;
        cp16(smem_u32(sB + row * ASTR + ch * 8),
             BT + (size_t)(bn + row) * K + kc * 64 + ch * 8);
    }
}

template <int EPI>
__global__ __launch_bounds__(256, 1)
void gemm_mma(const __nv_bfloat16* __restrict__ A, const __nv_bfloat16* __restrict__ BT,
              const float* __restrict__ bias, const float* __restrict__ res,
              void* __restrict__ Cout, int M, int N, int K) {
    extern __shared__ __align__(16) __nv_bfloat16 smem[];
    const int tid  = threadIdx.x;
    const int lane = tid & 31, warp = tid >> 5;
    const int wm = warp >> 2, wn = warp & 3;
    const int gq = lane >> 2, tq = lane & 3;
    const int l15 = lane & 15;
    const int arow = l15, asel = lane >> 4;
    const int g  = lane >> 3, r8 = lane & 7;
    const int brow_off = (g >> 1) * 8 + r8;
    const int bcol_off = (g & 1) * 8;
    const int bm = blockIdx.y << 7;
    const int bn = blockIdx.x << 8;
    const int NC = K >> 6;

    float c[4][8][4];
    #pragma unroll
    for (int i = 0; i < 4; i++)
        #pragma unroll
        for (int j = 0; j < 8; j++)
            #pragma unroll
            for (int k = 0; k < 4; k++) c[i][j][k] = 0.f;

    issue_tile(A, BT, smem,       bm, bn, 0, K, tid); CP_COMMIT();
    issue_tile(A, BT, smem + STG, bm, bn, 1, K, tid); CP_COMMIT();

    int st = 0;
    for (int kc = 0; kc < NC; kc++) {
        CP_WAIT1();
        __syncthreads();
        if (kc + 2 < NC) {
            int nst = st + 2; if (nst >= 3) nst -= 3;
            issue_tile(A, BT, smem + nst * STG, bm, bn, kc + 2, K, tid);
        }
        CP_COMMIT();
        const __nv_bfloat16* sa = smem + st * STG + (size_t)(wm * 64) * ASTR;
        const __nv_bfloat16* sb = smem + st * STG + (size_t)128 * ASTR + (size_t)(wn * 64) * ASTR;
        #pragma unroll
        for (int ks = 0; ks < 4; ks++) {
            uint32_t af[4][4], bf[4][4];
            #pragma unroll
            for (int mt = 0; mt < 4; mt++)
                ldsm_x4(af[mt], smem_u32(sa + (mt * 16 + arow) * ASTR + ks * 16 + asel * 8));
            #pragma unroll
            for (int np = 0; np < 4; np++)
                ldsm_x4(bf[np], smem_u32(sb + (np * 16 + brow_off) * ASTR + ks * 16 + bcol_off));
            #pragma unroll
            for (int mt = 0; mt < 4; mt++)
                #pragma unroll
                for (int np = 0; np < 4; np++) {
                    mma_bf16(c[mt][2 * np + 0], af[mt], bf[np] + 0);
                    mma_bf16(c[mt][2 * np + 1], af[mt], bf[np] + 2);
                }
        }
        if (++st >= 3) st = 0;
    }

    // ---- epilogue ----
    #pragma unroll
    for (int nt = 0; nt < 8; nt++) {
        const int col = bn + wn * 64 + nt * 8 + 2 * tq;
        const float bx = bias[col], by = bias[col + 1];
        #pragma unroll
        for (int mt = 0; mt < 4; mt++) {
            const int row0 = bm + wm * 64 + mt * 16 + gq;
            #pragma unroll
            for (int half = 0; half < 2; half++) {
                const int row = row0 + half * 8;
                float vx = c[mt][nt][half * 2 + 0] + bx;
                float vy = c[mt][nt][half * 2 + 1] + by;
                if (EPI == 1) {
                    vx = 0.5f * vx * (1.0f + erff(vx * 0.70710678118654752f));
                    vy = 0.5f * vy * (1.0f + erff(vy * 0.70710678118654752f));
                }
                if (EPI == 2) {
                    const float2 rv = *(const float2*)(res + (size_t)row * N + col);
                    float2 o; o.x = vx + rv.x; o.y = vy + rv.y;
                    *(float2*)((float*)Cout + (size_t)row * N + col) = o;
                } else {
                    *(uint32_t*)((__nv_bfloat16*)Cout + (size_t)row * N + col) =
                        pack_bf16(vx, vy);
                }
            }
        }
    }
}

// ---------------- Flash attention: 3-buffer ring, ONE barrier per tile -----------
#define KVS 72
#define NT  (NN / 64)

__global__ __launch_bounds__(256, 2)
void attn_mma(const __nv_bfloat16* __restrict__ qkv, __nv_bfloat16* __restrict__ out) {
    __shared__ __nv_bfloat16 Kb[3][64 * KVS];
    __shared__ __nv_bfloat16 Vb[3][64 * KVS];
    const int tid  = threadIdx.x;
    const int lane = tid & 31, warp = tid >> 5;
    const int gq = lane >> 2, tq = lane & 3;
    const int g  = lane >> 3, r8 = lane & 7;
    const int krow_off = (g >> 1) * 8 + r8;      // K ldsm.x4 pairing (nt pairs)
    const int kcol_off = (g & 1) * 8;
    const int vrow_off = (g & 1) * 8 + r8;       // V ldsm.x4.trans pairing (dt pairs)
    const int vcol_off = (g >> 1) * 8;
    const int bh = blockIdx.y;
    const int b = bh >> 4, h = bh & 15;
    const int q0 = blockIdx.x * 128;

    // per-buffer ldmatrix base addresses (hoisted; inner loops use immediates)
    uint32_t kbase[3], vbase[3];
    #pragma unroll
    for (int s = 0; s < 3; s++) {
        kbase[s] = smem_u32(&Kb[s][krow_off * KVS + kcol_off]);
        vbase[s] = smem_u32(&Vb[s][vrow_off * KVS + vcol_off]);
    }

    // ---- Q fragments, pre-scaled by D^-0.5 * log2(e), packed bf16x2 ----
    const float qsc = 0.125f * 1.4426950408889634f;
    uint32_t aq[4][4];
    {
        const __nv_bfloat16* r0 = qkv + (size_t)(b * NN + q0 + warp * 16 + gq) * 3072 + h * 64;
        const __nv_bfloat16* r1 = r0 + (size_t)8 * 3072;
        #pragma unroll
        for (int ks = 0; ks < 4; ks++) {
            aq[ks][0] = scale_bf16x2(*(const uint32_t*)(r0 + ks * 16 + 2 * tq), qsc);
            aq[ks][1] = scale_bf16x2(*(const uint32_t*)(r1 + ks * 16 + 2 * tq), qsc);
            aq[ks][2] = scale_bf16x2(*(const uint32_t*)(r0 + ks * 16 + 2 * tq + 8), qsc);
            aq[ks][3] = scale_bf16x2(*(const uint32_t*)(r1 + ks * 16 + 2 * tq + 8), qsc);
        }
    }

    float oc[8][4];
    #pragma unroll
    for (int i = 0; i < 8; i++)
        #pragma unroll
        for (int j = 0; j < 4; j++) oc[i][j] = 0.f;
    float m0 = -1e30f, m1 = -1e30f, l0 = 0.f, l1 = 0.f;

    auto issue_kv = [&](int buf, int kt) {
        #pragma unroll
        for (int it = 0; it < 2; it++) {
            const int e = it * 256 + tid;
            const int row = e >> 3, ch = e & 7;
            const size_t gbase = (size_t)(b * NN + kt * 64 + row) * 3072 + h * 64 + ch * 8;
            cp16(smem_u32(&Kb[buf][row * KVS + ch * 8]), qkv + gbase + 1024);
            cp16(smem_u32(&Vb[buf][row * KVS + ch * 8]), qkv + gbase + 2048);
        }
    };

    issue_kv(0, 0); CP_COMMIT();
    issue_kv(1, 1); CP_COMMIT();

    int st = 0;  // stage of tile kt
    for (int kt = 0; kt < NT; kt++) {
        CP_WAIT1();          // tile kt resident
        __syncthreads();     // all warps finished tile kt-1 (stage being refilled next)
        if (kt + 2 < NT) {
            int nst = st + 2; if (nst >= 3) nst -= 3;
            issue_kv(nst, kt + 2);
        }
        CP_COMMIT();
        const uint32_t ka = kbase[st];
        const uint32_t va = vbase[st];

        // ---- S = Q_scaled K^T (log2 domain) ----
        float sc[8][4];
        #pragma unroll
        for (int i = 0; i < 8; i++)
            #pragma unroll
            for (int j = 0; j < 4; j++) sc[i][j] = 0.f;
        #pragma unroll
        for (int ks = 0; ks < 4; ks++) {
            #pragma unroll
            for (int np = 0; np < 4; np++) {
                uint32_t b4[4];
                ldsm_x4(b4, ka + (uint32_t)((np * 16 * KVS + ks * 16) * 2));
                mma_bf16(sc[2 * np + 0], aq[ks], b4 + 0);
                mma_bf16(sc[2 * np + 1], aq[ks], b4 + 2);
            }
        }

        // ---- online softmax (exp2 domain) ----
        float mx0 = -1e30f, mx1 = -1e30f;
        #pragma unroll
        for (int nt = 0; nt < 8; nt++) {
            mx0 = fmaxf(mx0, fmaxf(sc[nt][0], sc[nt][1]));
            mx1 = fmaxf(mx1, fmaxf(sc[nt][2], sc[nt][3]));
        }
        mx0 = fmaxf(mx0, __shfl_xor_sync(0xffffffffu, mx0, 1));
        mx0 = fmaxf(mx0, __shfl_xor_sync(0xffffffffu, mx0, 2));
        mx1 = fmaxf(mx1, __shfl_xor_sync(0xffffffffu, mx1, 1));
        mx1 = fmaxf(mx1, __shfl_xor_sync(0xffffffffu, mx1, 2));
        const float mn0 = fmaxf(m0, mx0), mn1 = fmaxf(m1, mx1);
        const float f0 = ex2(m0 - mn0), f1 = ex2(m1 - mn1);
        m0 = mn0; m1 = mn1;
        l0 *= f0; l1 *= f1;
        #pragma unroll
        for (int dt = 0; dt < 8; dt++) {
            oc[dt][0] *= f0; oc[dt][1] *= f0;
            oc[dt][2] *= f1; oc[dt][3] *= f1;
        }

        // ---- P = exp2(S - m); PV accumulate ----
        #pragma unroll
        for (int j = 0; j < 4; j++) {
            const int t0 = 2 * j, t1 = 2 * j + 1;
            const float p00 = ex2(sc[t0][0] - m0), p01 = ex2(sc[t0][1] - m0);
            const float p02 = ex2(sc[t0][2] - m1), p03 = ex2(sc[t0][3] - m1);
            const float p10 = ex2(sc[t1][0] - m0), p11 = ex2(sc[t1][1] - m0);
            const float p12 = ex2(sc[t1][2] - m1), p13 = ex2(sc[t1][3] - m1);
            l0 += p00 + p01 + p10 + p11;
            l1 += p02 + p03 + p12 + p13;
            uint32_t pa[4] = { pack_bf16(p00, p01), pack_bf16(p02, p03),
                               pack_bf16(p10, p11), pack_bf16(p12, p13) };
            #pragma unroll
            for (int dp = 0; dp < 4; dp++) {
                uint32_t b4[4];
                ldsm_x4t(b4, va + (uint32_t)((16 * j * KVS + dp * 16) * 2));
                mma_bf16(oc[2 * dp + 0], pa, b4 + 0);
                mma_bf16(oc[2 * dp + 1], pa, b4 + 2);
            }
        }
        if (++st >= 3) st = 0;
    }

    // ---- finalize ----
    l0 += __shfl_xor_sync(0xffffffffu, l0, 1);
    l0 += __shfl_xor_sync(0xffffffffu, l0, 2);
    l1 += __shfl_xor_sync(0xffffffffu, l1, 1);
    l1 += __shfl_xor_sync(0xffffffffu, l1, 2);
    const float inv0 = 1.f / l0, inv1 = 1.f / l1;
    const int row0 = b * NN + q0 + warp * 16 + gq;
    __nv_bfloat16* o0 = out + (size_t)row0 * EE + h * 64;
    __nv_bfloat16* o1 = o0 + (size_t)8 * EE;
    #pragma unroll
    for (int dt = 0; dt < 8; dt++) {
        *(uint32_t*)(o0 + dt * 8 + 2 * tq) = pack_bf16(oc[dt][0] * inv0, oc[dt][1] * inv0);
        *(uint32_t*)(o1 + dt * 8 + 2 * tq) = pack_bf16(oc[dt][2] * inv1, oc[dt][3] * inv1);
    }
}

// ---------------- host launch ---------------------------------------------------
extern "C" void kernel_launch(void* const* d_in, const int* in_sizes, int n_in,
                              void* d_out, int out_size) {
    const float* x      = (const float*)d_in[0];
    const float* w_qkv  = (const float*)d_in[1];
    const float* b_qkv  = (const float*)d_in[2];
    const float* w_proj = (const float*)d_in[3];
    const float* b_proj = (const float*)d_in[4];
    const float* g1     = (const float*)d_in[5];
    const float* beta1  = (const float*)d_in[6];
    const float* g2     = (const float*)d_in[7];
    const float* beta2  = (const float*)d_in[8];
    const float* w_fc1  = (const float*)d_in[9];
    const float* b_fc1  = (const float*)d_in[10];
    const float* w_fc2  = (const float*)d_in[11];
    const float* b_fc2  = (const float*)d_in[12];
    float* out = (float*)d_out;

    __nv_bfloat16 *h, *qkv, *attn, *mlp, *wqkvT, *wprojT, *wfc1T, *wfc2T;
    float* x1;
    cudaGetSymbolAddress((void**)&h,      g_h);
    cudaGetSymbolAddress((void**)&qkv,    g_qkv);
    cudaGetSymbolAddress((void**)&attn,   g_attn);
    cudaGetSymbolAddress((void**)&x1,     g_x1);
    cudaGetSymbolAddress((void**)&mlp,    g_mlp);
    cudaGetSymbolAddress((void**)&wqkvT,  g_wqkvT);
    cudaGetSymbolAddress((void**)&wprojT, g_wprojT);
    cudaGetSymbolAddress((void**)&wfc1T,  g_wfc1T);
    cudaGetSymbolAddress((void**)&wfc2T,  g_wfc2T);

    cudaFuncSetAttribute(gemm_mma<0>, cudaFuncAttributeMaxDynamicSharedMemorySize, GEMM_SMEM_BYTES);
    cudaFuncSetAttribute(gemm_mma<1>, cudaFuncAttributeMaxDynamicSharedMemorySize, GEMM_SMEM_BYTES);
    cudaFuncSetAttribute(gemm_mma<2>, cudaFuncAttributeMaxDynamicSharedMemorySize, GEMM_SMEM_BYTES);

    transpose_all<<<T_FC2, dim3(32, 8)>>>(w_qkv, w_proj, w_fc1, w_fc2,
                                          wqkvT, wprojT, wfc1T, wfc2T);

    // 1. h = LN(x) -> bf16
    ln_kernel<<<MR, 256>>>(x, g1, beta1, h);
    // 2. qkv = h @ w_qkv + b_qkv -> bf16
    gemm_mma<0><<<dim3(3 * EE / 256, MR / 128), 256, GEMM_SMEM_BYTES>>>(
        h, wqkvT, b_qkv, nullptr, qkv, MR, 3 * EE, EE);
    // 3. attention -> bf16
    attn_mma<<<dim3(NN / 128, BB * HH), 256>>>(qkv, attn);
    // 4. x1 = attn @ w_proj + b_proj + x -> fp32
    gemm_mma<2><<<dim3(EE / 256, MR / 128), 256, GEMM_SMEM_BYTES>>>(
        attn, wprojT, b_proj, x, x1, MR, EE, EE);
    // 5. h = LN(x1) -> bf16
    ln_kernel<<<MR, 256>>>(x1, g2, beta2, h);
    // 6. mlp = gelu(h @ w_fc1 + b_fc1) -> bf16
    gemm_mma<1><<<dim3(MLPD / 256, MR / 128), 256, GEMM_SMEM_BYTES>>>(
        h, wfc1T, b_fc1, nullptr, mlp, MR, MLPD, EE);
    // 7. out = mlp @ w_fc2 + b_fc2 + x1 -> fp32
    gemm_mma<2><<<dim3(EE / 256, MR / 128), 256, GEMM_SMEM_BYTES>>>(
        mlp, wfc2T, b_fc2, x1, out, MR, EE, MLPD);
}

// round 10
// speedup vs baseline: 7.4479x; 1.0036x over previous
#include <cuda_runtime.h>
#include <cuda_bf16.h>
#include <math.h>
#include <stdint.h>

// Problem constants
#define BB   2
#define NN   2048
#define EE   1024
#define HH   16
#define MLPD 4096
#define MR   (BB * NN)   // 4096 token rows

// ---------------- scratch (static device globals; no allocation) ----------------
__device__ __nv_bfloat16 g_h[MR * EE];               // LN output (bf16)
__device__ __nv_bfloat16 g_qkv[MR * 3 * EE];         // QKV (bf16)
__device__ __nv_bfloat16 g_attn[MR * EE];            // attention out (bf16)
__device__ float         g_x1[MR * EE];              // residual 1 (fp32)
__device__ __nv_bfloat16 g_mlp[(size_t)MR * MLPD];   // GELU(fc1) (bf16)
__device__ __nv_bfloat16 g_wqkvT[3 * EE * EE];       // transposed weights [N,K] bf16
__device__ __nv_bfloat16 g_wprojT[EE * EE];
__device__ __nv_bfloat16 g_wfc1T[(size_t)MLPD * EE];
__device__ __nv_bfloat16 g_wfc2T[(size_t)EE * MLPD];

// ======================= helpers =================================
__device__ __forceinline__ uint32_t smem_u32(const void* p) {
    uint32_t a;
    asm("{ .reg .u64 t; cvta.to.shared.u64 t, %1; cvt.u32.u64 %0, t; }" : "=r"(a) : "l"(p));
    return a;
}
__device__ __forceinline__ float ex2(float x) {
    float r;
    asm("ex2.approx.ftz.f32 %0, %1;" : "=f"(r) : "f"(x));
    return r;
}
__device__ __forceinline__ uint32_t pack_bf16(float lo, float hi) {
    uint32_t r;
    asm("cvt.rn.bf16x2.f32 %0, %1, %2;" : "=r"(r) : "f"(hi), "f"(lo));
    return r;
}
__device__ __forceinline__ uint32_t scale_bf16x2(uint32_t v, float s) {
    const __nv_bfloat162 b = *reinterpret_cast<const __nv_bfloat162*>(&v);
    return pack_bf16(__bfloat162float(b.x) * s, __bfloat162float(b.y) * s);
}
__device__ __forceinline__ void cp16(uint32_t dst, const void* src) {
    asm volatile("cp.async.cg.shared.global [%0], [%1], 16;" :: "r"(dst), "l"(src));
}
#define CP_COMMIT() asm volatile("cp.async.commit_group;" ::: "memory")
#define CP_WAIT1()  asm volatile("cp.async.wait_group 1;" ::: "memory")

__device__ __forceinline__ void mma_bf16(float* c, const uint32_t* a, const uint32_t* b) {
    asm volatile(
        "mma.sync.aligned.m16n8k16.row.col.f32.bf16.bf16.f32 "
        "{%0,%1,%2,%3}, {%4,%5,%6,%7}, {%8,%9}, {%0,%1,%2,%3};"
        : "+f"(c[0]), "+f"(c[1]), "+f"(c[2]), "+f"(c[3])
        : "r"(a[0]), "r"(a[1]), "r"(a[2]), "r"(a[3]), "r"(b[0]), "r"(b[1]));
}
__device__ __forceinline__ void ldsm_x4(uint32_t* r, uint32_t addr) {
    asm volatile("ldmatrix.sync.aligned.m8n8.x4.shared.b16 {%0,%1,%2,%3}, [%4];"
                 : "=r"(r[0]), "=r"(r[1]), "=r"(r[2]), "=r"(r[3]) : "r"(addr));
}
__device__ __forceinline__ void ldsm_x4t(uint32_t* r, uint32_t addr) {
    asm volatile("ldmatrix.sync.aligned.m8n8.x4.trans.shared.b16 {%0,%1,%2,%3}, [%4];"
                 : "=r"(r[0]), "=r"(r[1]), "=r"(r[2]), "=r"(r[3]) : "r"(addr));
}

// ---------------- fused transpose of all 4 weights: one launch -------------------
#define T_QKV  3072
#define T_PROJ (T_QKV + 1024)
#define T_FC1  (T_PROJ + 4096)
#define T_FC2  (T_FC1 + 4096)

__global__ void transpose_all(const float* __restrict__ w0, const float* __restrict__ w1,
                              const float* __restrict__ w2, const float* __restrict__ w3,
                              __nv_bfloat16* __restrict__ o0, __nv_bfloat16* __restrict__ o1,
                              __nv_bfloat16* __restrict__ o2, __nv_bfloat16* __restrict__ o3) {
    __shared__ float t[32][33];
    int tt = blockIdx.x;
    const float* in;
    __nv_bfloat16* out;
    int R, C;
    if (tt < T_QKV)       { in = w0; out = o0; R = EE;   C = 3 * EE; }
    else if (tt < T_PROJ) { in = w1; out = o1; R = EE;   C = EE;   tt -= T_QKV;  }
    else if (tt < T_FC1)  { in = w2; out = o2; R = EE;   C = MLPD; tt -= T_PROJ; }
    else                  { in = w3; out = o3; R = MLPD; C = EE;   tt -= T_FC1;  }
    const int ctiles = C >> 5;
    const int bx = tt % ctiles, by = tt / ctiles;

    const int c = bx * 32 + threadIdx.x;
    const int r0 = by * 32;
    #pragma unroll
    for (int i = threadIdx.y; i < 32; i += 8)
        t[i][threadIdx.x] = in[(size_t)(r0 + i) * C + c];
    __syncthreads();
    const int rc = by * 32 + threadIdx.x;
    const int c0 = bx * 32;
    #pragma unroll
    for (int i = threadIdx.y; i < 32; i += 8)
        out[(size_t)(c0 + i) * R + rc] = __float2bfloat16_rn(t[threadIdx.x][i]);
}

// ---------------- LayerNorm fp32 -> bf16 -----------------------------------------
__global__ void ln_kernel(const float* __restrict__ x, const float* __restrict__ g,
                          const float* __restrict__ beta,
                          __nv_bfloat16* __restrict__ out) {
    __shared__ float sh[8];
    const int row = blockIdx.x;
    const int tid = threadIdx.x;
    const float4 v = ((const float4*)(x + (size_t)row * EE))[tid];

    float s = v.x + v.y + v.z + v.w;
    #pragma unroll
    for (int o = 16; o; o >>= 1) s += __shfl_down_sync(0xffffffffu, s, o);
    if ((tid & 31) == 0) sh[tid >> 5] = s;
    __syncthreads();
    if (tid < 32) {
        float t = (tid < 8) ? sh[tid] : 0.f;
        #pragma unroll
        for (int o = 4; o; o >>= 1) t += __shfl_down_sync(0xffffffffu, t, o);
        if (tid == 0) sh[0] = t;
    }
    __syncthreads();
    const float mu = sh[0] * (1.0f / EE);
    __syncthreads();

    float dx = v.x - mu, dy = v.y - mu, dz = v.z - mu, dw = v.w - mu;
    float q = dx * dx + dy * dy + dz * dz + dw * dw;
    #pragma unroll
    for (int o = 16; o; o >>= 1) q += __shfl_down_sync(0xffffffffu, q, o);
    if ((tid & 31) == 0) sh[tid >> 5] = q;
    __syncthreads();
    if (tid < 32) {
        float t = (tid < 8) ? sh[tid] : 0.f;
        #pragma unroll
        for (int o = 4; o; o >>= 1) t += __shfl_down_sync(0xffffffffu, t, o);
        if (tid == 0) sh[0] = t;
    }
    __syncthreads();
    const float rstd = rsqrtf(sh[0] * (1.0f / EE) + 1e-5f);

    const float4 gv = ((const float4*)g)[tid];
    const float4 bv = ((const float4*)beta)[tid];
    uint2 o;
    o.x = pack_bf16(dx * rstd * gv.x + bv.x, dy * rstd * gv.y + bv.y);
    o.y = pack_bf16(dz * rstd * gv.z + bv.z, dw * rstd * gv.w + bv.w);
    ((uint2*)(out + (size_t)row * EE))[tid] = o;
}

// ---------------- bf16 mma.sync GEMM: CTA 128x256, 3-stage, x4 ldmatrix ----------
#define ASTR 72
#define STG  ((128 + 256) * ASTR)
#define GEMM_SMEM_BYTES (3 * STG * 2)

__device__ __forceinline__ void issue_tile(const __nv_bfloat16* __restrict__ A,
                                           const __nv_bfloat16* __restrict__ BT,
                                           __nv_bfloat16* stage, int bm, int bn,
                                           int kc, int K, int tid) {
    __nv_bfloat16* sA = stage;
    __nv_bfloat16* sB = stage + 128 * ASTR;
    #pragma unroll
    for (int p = 0; p < 4; p++) {
        const int e = p * 256 + tid;
        const int row = e >> 3, ch = e & 7;
        cp16(smem_u32(sA + row * ASTR + ch * 8),
             A + (size_t)(bm + row) * K + kc * 64 + ch * 8);
    }
    #pragma unroll
    for (int p = 0; p < 8; p++) {
        const int e = p * 256 + tid;
        const int row = e >> 3, ch = e & 7;
        cp16(smem_u32(sB + row * ASTR + ch * 8),
             BT + (size_t)(bn + row) * K + kc * 64 + ch * 8);
    }
}

template <int EPI>
__global__ __launch_bounds__(256, 1)
void gemm_mma(const __nv_bfloat16* __restrict__ A, const __nv_bfloat16* __restrict__ BT,
              const float* __restrict__ bias, const float* __restrict__ res,
              void* __restrict__ Cout, int M, int N, int K) {
    extern __shared__ __align__(16) __nv_bfloat16 smem[];
    const int tid  = threadIdx.x;
    const int lane = tid & 31, warp = tid >> 5;
    const int wm = warp >> 2, wn = warp & 3;
    const int gq = lane >> 2, tq = lane & 3;
    const int l15 = lane & 15;
    const int arow = l15, asel = lane >> 4;
    const int g  = lane >> 3, r8 = lane & 7;
    const int brow_off = (g >> 1) * 8 + r8;
    const int bcol_off = (g & 1) * 8;
    const int bm = blockIdx.y << 7;
    const int bn = blockIdx.x << 8;
    const int NC = K >> 6;

    float c[4][8][4];
    #pragma unroll
    for (int i = 0; i < 4; i++)
        #pragma unroll
        for (int j = 0; j < 8; j++)
            #pragma unroll
            for (int k = 0; k < 4; k++) c[i][j][k] = 0.f;

    issue_tile(A, BT, smem,       bm, bn, 0, K, tid); CP_COMMIT();
    issue_tile(A, BT, smem + STG, bm, bn, 1, K, tid); CP_COMMIT();

    int st = 0;
    for (int kc = 0; kc < NC; kc++) {
        CP_WAIT1();
        __syncthreads();
        if (kc + 2 < NC) {
            int nst = st + 2; if (nst >= 3) nst -= 3;
            issue_tile(A, BT, smem + nst * STG, bm, bn, kc + 2, K, tid);
        }
        CP_COMMIT();
        const __nv_bfloat16* sa = smem + st * STG + (size_t)(wm * 64) * ASTR;
        const __nv_bfloat16* sb = smem + st * STG + (size_t)128 * ASTR + (size_t)(wn * 64) * ASTR;
        #pragma unroll
        for (int ks = 0; ks < 4; ks++) {
            uint32_t af[4][4], bf[4][4];
            #pragma unroll
            for (int mt = 0; mt < 4; mt++)
                ldsm_x4(af[mt], smem_u32(sa + (mt * 16 + arow) * ASTR + ks * 16 + asel * 8));
            #pragma unroll
            for (int np = 0; np < 4; np++)
                ldsm_x4(bf[np], smem_u32(sb + (np * 16 + brow_off) * ASTR + ks * 16 + bcol_off));
            #pragma unroll
            for (int mt = 0; mt < 4; mt++)
                #pragma unroll
                for (int np = 0; np < 4; np++) {
                    mma_bf16(c[mt][2 * np + 0], af[mt], bf[np] + 0);
                    mma_bf16(c[mt][2 * np + 1], af[mt], bf[np] + 2);
                }
        }
        if (++st >= 3) st = 0;
    }

    // ---- epilogue ----
    #pragma unroll
    for (int nt = 0; nt < 8; nt++) {
        const int col = bn + wn * 64 + nt * 8 + 2 * tq;
        const float bx = bias[col], by = bias[col + 1];
        #pragma unroll
        for (int mt = 0; mt < 4; mt++) {
            const int row0 = bm + wm * 64 + mt * 16 + gq;
            #pragma unroll
            for (int half = 0; half < 2; half++) {
                const int row = row0 + half * 8;
                float vx = c[mt][nt][half * 2 + 0] + bx;
                float vy = c[mt][nt][half * 2 + 1] + by;
                if (EPI == 1) {
                    vx = 0.5f * vx * (1.0f + erff(vx * 0.70710678118654752f));
                    vy = 0.5f * vy * (1.0f + erff(vy * 0.70710678118654752f));
                }
                if (EPI == 2) {
                    const float2 rv = *(const float2*)(res + (size_t)row * N + col);
                    float2 o; o.x = vx + rv.x; o.y = vy + rv.y;
                    *(float2*)((float*)Cout + (size_t)row * N + col) = o;
                } else {
                    *(uint32_t*)((__nv_bfloat16*)Cout + (size_t)row * N + col) =
                        pack_bf16(vx, vy);
                }
            }
        }
    }
}

// ---------------- Flash attention: 256 queries/CTA, 32 rows/warp -----------------
// 3-buffer K/V ring, ONE barrier per tile. Each warp owns two 16-row m-tiles and
// shares every loaded K/V fragment across both (halves smem read amplification).
#define KVS 72
#define NT  (NN / 64)

__global__ __launch_bounds__(256, 1)
void attn_mma(const __nv_bfloat16* __restrict__ qkv, __nv_bfloat16* __restrict__ out) {
    __shared__ __nv_bfloat16 Kb[3][64 * KVS];
    __shared__ __nv_bfloat16 Vb[3][64 * KVS];
    const int tid  = threadIdx.x;
    const int lane = tid & 31, warp = tid >> 5;
    const int gq = lane >> 2, tq = lane & 3;
    const int g  = lane >> 3, r8 = lane & 7;
    const int krow_off = (g >> 1) * 8 + r8;      // K ldsm.x4 pairing (nt pairs)
    const int kcol_off = (g & 1) * 8;
    const int vrow_off = (g & 1) * 8 + r8;       // V ldsm.x4.trans pairing (dt pairs)
    const int vcol_off = (g >> 1) * 8;
    const int bh = blockIdx.y;
    const int b = bh >> 4, h = bh & 15;
    const int q0 = blockIdx.x * 256;

    // per-buffer ldmatrix base addresses
    uint32_t kbase[3], vbase[3];
    #pragma unroll
    for (int s = 0; s < 3; s++) {
        kbase[s] = smem_u32(&Kb[s][krow_off * KVS + kcol_off]);
        vbase[s] = smem_u32(&Vb[s][vrow_off * KVS + vcol_off]);
    }

    // ---- Q fragments (2 m-tiles), pre-scaled by D^-0.5 * log2(e) ----
    const float qsc = 0.125f * 1.4426950408889634f;
    uint32_t aq[2][4][4];
    #pragma unroll
    for (int mi = 0; mi < 2; mi++) {
        const __nv_bfloat16* r0 =
            qkv + (size_t)(b * NN + q0 + warp * 32 + mi * 16 + gq) * 3072 + h * 64;
        const __nv_bfloat16* r1 = r0 + (size_t)8 * 3072;
        #pragma unroll
        for (int ks = 0; ks < 4; ks++) {
            aq[mi][ks][0] = scale_bf16x2(*(const uint32_t*)(r0 + ks * 16 + 2 * tq), qsc);
            aq[mi][ks][1] = scale_bf16x2(*(const uint32_t*)(r1 + ks * 16 + 2 * tq), qsc);
            aq[mi][ks][2] = scale_bf16x2(*(const uint32_t*)(r0 + ks * 16 + 2 * tq + 8), qsc);
            aq[mi][ks][3] = scale_bf16x2(*(const uint32_t*)(r1 + ks * 16 + 2 * tq + 8), qsc);
        }
    }

    float oc[2][8][4];
    #pragma unroll
    for (int mi = 0; mi < 2; mi++)
        #pragma unroll
        for (int i = 0; i < 8; i++)
            #pragma unroll
            for (int j = 0; j < 4; j++) oc[mi][i][j] = 0.f;
    float mrow[2][2] = { {-1e30f, -1e30f}, {-1e30f, -1e30f} };
    float lrow[2][2] = { {0.f, 0.f}, {0.f, 0.f} };

    auto issue_kv = [&](int buf, int kt) {
        #pragma unroll
        for (int it = 0; it < 2; it++) {
            const int e = it * 256 + tid;
            const int row = e >> 3, ch = e & 7;
            const size_t gbase = (size_t)(b * NN + kt * 64 + row) * 3072 + h * 64 + ch * 8;
            cp16(smem_u32(&Kb[buf][row * KVS + ch * 8]), qkv + gbase + 1024);
            cp16(smem_u32(&Vb[buf][row * KVS + ch * 8]), qkv + gbase + 2048);
        }
    };

    issue_kv(0, 0); CP_COMMIT();
    issue_kv(1, 1); CP_COMMIT();

    int st = 0;  // stage of tile kt
    for (int kt = 0; kt < NT; kt++) {
        CP_WAIT1();
        __syncthreads();
        if (kt + 2 < NT) {
            int nst = st + 2; if (nst >= 3) nst -= 3;
            issue_kv(nst, kt + 2);
        }
        CP_COMMIT();
        const uint32_t ka = kbase[st];
        const uint32_t va = vbase[st];

        // ---- S = Q_scaled K^T (log2 domain), both m-tiles per K fragment ----
        float sc[2][8][4];
        #pragma unroll
        for (int mi = 0; mi < 2; mi++)
            #pragma unroll
            for (int i = 0; i < 8; i++)
                #pragma unroll
                for (int j = 0; j < 4; j++) sc[mi][i][j] = 0.f;
        #pragma unroll
        for (int ks = 0; ks < 4; ks++) {
            #pragma unroll
            for (int np = 0; np < 4; np++) {
                uint32_t b4[4];
                ldsm_x4(b4, ka + (uint32_t)((np * 16 * KVS + ks * 16) * 2));
                #pragma unroll
                for (int mi = 0; mi < 2; mi++) {
                    mma_bf16(sc[mi][2 * np + 0], aq[mi][ks], b4 + 0);
                    mma_bf16(sc[mi][2 * np + 1], aq[mi][ks], b4 + 2);
                }
            }
        }

        // ---- online softmax (exp2 domain), per m-tile ----
        float f[2][2];
        #pragma unroll
        for (int mi = 0; mi < 2; mi++) {
            float mx0 = -1e30f, mx1 = -1e30f;
            #pragma unroll
            for (int nt = 0; nt < 8; nt++) {
                mx0 = fmaxf(mx0, fmaxf(sc[mi][nt][0], sc[mi][nt][1]));
                mx1 = fmaxf(mx1, fmaxf(sc[mi][nt][2], sc[mi][nt][3]));
            }
            mx0 = fmaxf(mx0, __shfl_xor_sync(0xffffffffu, mx0, 1));
            mx0 = fmaxf(mx0, __shfl_xor_sync(0xffffffffu, mx0, 2));
            mx1 = fmaxf(mx1, __shfl_xor_sync(0xffffffffu, mx1, 1));
            mx1 = fmaxf(mx1, __shfl_xor_sync(0xffffffffu, mx1, 2));
            const float mn0 = fmaxf(mrow[mi][0], mx0);
            const float mn1 = fmaxf(mrow[mi][1], mx1);
            f[mi][0] = ex2(mrow[mi][0] - mn0);
            f[mi][1] = ex2(mrow[mi][1] - mn1);
            mrow[mi][0] = mn0; mrow[mi][1] = mn1;
            lrow[mi][0] *= f[mi][0]; lrow[mi][1] *= f[mi][1];
            #pragma unroll
            for (int dt = 0; dt < 8; dt++) {
                oc[mi][dt][0] *= f[mi][0]; oc[mi][dt][1] *= f[mi][0];
                oc[mi][dt][2] *= f[mi][1]; oc[mi][dt][3] *= f[mi][1];
            }
        }

        // ---- P = exp2(S - m); PV accumulate, both m-tiles per V fragment ----
        #pragma unroll
        for (int j = 0; j < 4; j++) {
            uint32_t pa[2][4];
            #pragma unroll
            for (int mi = 0; mi < 2; mi++) {
                const int t0 = 2 * j, t1 = 2 * j + 1;
                const float m0 = mrow[mi][0], m1 = mrow[mi][1];
                const float p00 = ex2(sc[mi][t0][0] - m0), p01 = ex2(sc[mi][t0][1] - m0);
                const float p02 = ex2(sc[mi][t0][2] - m1), p03 = ex2(sc[mi][t0][3] - m1);
                const float p10 = ex2(sc[mi][t1][0] - m0), p11 = ex2(sc[mi][t1][1] - m0);
                const float p12 = ex2(sc[mi][t1][2] - m1), p13 = ex2(sc[mi][t1][3] - m1);
                lrow[mi][0] += p00 + p01 + p10 + p11;
                lrow[mi][1] += p02 + p03 + p12 + p13;
                pa[mi][0] = pack_bf16(p00, p01); pa[mi][1] = pack_bf16(p02, p03);
                pa[mi][2] = pack_bf16(p10, p11); pa[mi][3] = pack_bf16(p12, p13);
            }
            #pragma unroll
            for (int dp = 0; dp < 4; dp++) {
                uint32_t b4[4];
                ldsm_x4t(b4, va + (uint32_t)((16 * j * KVS + dp * 16) * 2));
                #pragma unroll
                for (int mi = 0; mi < 2; mi++) {
                    mma_bf16(oc[mi][2 * dp + 0], pa[mi], b4 + 0);
                    mma_bf16(oc[mi][2 * dp + 1], pa[mi], b4 + 2);
                }
            }
        }
        if (++st >= 3) st = 0;
    }

    // ---- finalize ----
    #pragma unroll
    for (int mi = 0; mi < 2; mi++) {
        float l0 = lrow[mi][0], l1 = lrow[mi][1];
        l0 += __shfl_xor_sync(0xffffffffu, l0, 1);
        l0 += __shfl_xor_sync(0xffffffffu, l0, 2);
        l1 += __shfl_xor_sync(0xffffffffu, l1, 1);
        l1 += __shfl_xor_sync(0xffffffffu, l1, 2);
        const float inv0 = 1.f / l0, inv1 = 1.f / l1;
        const int row0 = b * NN + q0 + warp * 32 + mi * 16 + gq;
        __nv_bfloat16* o0 = out + (size_t)row0 * EE + h * 64;
        __nv_bfloat16* o1 = o0 + (size_t)8 * EE;
        #pragma unroll
        for (int dt = 0; dt < 8; dt++) {
            *(uint32_t*)(o0 + dt * 8 + 2 * tq) =
                pack_bf16(oc[mi][dt][0] * inv0, oc[mi][dt][1] * inv0);
            *(uint32_t*)(o1 + dt * 8 + 2 * tq) =
                pack_bf16(oc[mi][dt][2] * inv1, oc[mi][dt][3] * inv1);
        }
    }
}

// ---------------- host launch ---------------------------------------------------
extern "C" void kernel_launch(void* const* d_in, const int* in_sizes, int n_in,
                              void* d_out, int out_size) {
    const float* x      = (const float*)d_in[0];
    const float* w_qkv  = (const float*)d_in[1];
    const float* b_qkv  = (const float*)d_in[2];
    const float* w_proj = (const float*)d_in[3];
    const float* b_proj = (const float*)d_in[4];
    const float* g1     = (const float*)d_in[5];
    const float* beta1  = (const float*)d_in[6];
    const float* g2     = (const float*)d_in[7];
    const float* beta2  = (const float*)d_in[8];
    const float* w_fc1  = (const float*)d_in[9];
    const float* b_fc1  = (const float*)d_in[10];
    const float* w_fc2  = (const float*)d_in[11];
    const float* b_fc2  = (const float*)d_in[12];
    float* out = (float*)d_out;

    __nv_bfloat16 *h, *qkv, *attn, *mlp, *wqkvT, *wprojT, *wfc1T, *wfc2T;
    float* x1;
    cudaGetSymbolAddress((void**)&h,      g_h);
    cudaGetSymbolAddress((void**)&qkv,    g_qkv);
    cudaGetSymbolAddress((void**)&attn,   g_attn);
    cudaGetSymbolAddress((void**)&x1,     g_x1);
    cudaGetSymbolAddress((void**)&mlp,    g_mlp);
    cudaGetSymbolAddress((void**)&wqkvT,  g_wqkvT);
    cudaGetSymbolAddress((void**)&wprojT, g_wprojT);
    cudaGetSymbolAddress((void**)&wfc1T,  g_wfc1T);
    cudaGetSymbolAddress((void**)&wfc2T,  g_wfc2T);

    cudaFuncSetAttribute(gemm_mma<0>, cudaFuncAttributeMaxDynamicSharedMemorySize, GEMM_SMEM_BYTES);
    cudaFuncSetAttribute(gemm_mma<1>, cudaFuncAttributeMaxDynamicSharedMemorySize, GEMM_SMEM_BYTES);
    cudaFuncSetAttribute(gemm_mma<2>, cudaFuncAttributeMaxDynamicSharedMemorySize, GEMM_SMEM_BYTES);

    transpose_all<<<T_FC2, dim3(32, 8)>>>(w_qkv, w_proj, w_fc1, w_fc2,
                                          wqkvT, wprojT, wfc1T, wfc2T);

    // 1. h = LN(x) -> bf16
    ln_kernel<<<MR, 256>>>(x, g1, beta1, h);
    // 2. qkv = h @ w_qkv + b_qkv -> bf16
    gemm_mma<0><<<dim3(3 * EE / 256, MR / 128), 256, GEMM_SMEM_BYTES>>>(
        h, wqkvT, b_qkv, nullptr, qkv, MR, 3 * EE, EE);
    // 3. attention -> bf16 (256 queries per CTA)
    attn_mma<<<dim3(NN / 256, BB * HH), 256>>>(qkv, attn);
    // 4. x1 = attn @ w_proj + b_proj + x -> fp32
    gemm_mma<2><<<dim3(EE / 256, MR / 128), 256, GEMM_SMEM_BYTES>>>(
        attn, wprojT, b_proj, x, x1, MR, EE, EE);
    // 5. h = LN(x1) -> bf16
    ln_kernel<<<MR, 256>>>(x1, g2, beta2, h);
    // 6. mlp = gelu(h @ w_fc1 + b_fc1) -> bf16
    gemm_mma<1><<<dim3(MLPD / 256, MR / 128), 256, GEMM_SMEM_BYTES>>>(
        h, wfc1T, b_fc1, nullptr, mlp, MR, MLPD, EE);
    // 7. out = mlp @ w_fc2 + b_fc2 + x1 -> fp32
    gemm_mma<2><<<dim3(EE / 256, MR / 128), 256, GEMM_SMEM_BYTES>>>(
        mlp, wfc2T, b_fc2, x1, out, MR, EE, MLPD);
}